// round 2
// baseline (speedup 1.0000x reference)
#include <cuda_runtime.h>
#include <cuda_bf16.h>

// Problem constants (fixed by the dataset)
#define NN 200000
#define UU 20000
#define HH 256

// ---------------- scratch (device globals; no runtime allocation) -------------
__device__ __align__(16) float    g_M  [HH * HH];      // Wq @ Wk^T
__device__ __align__(16) float    g_C1 [HH * HH];      // Wv @ W1[:, :H]^T
__device__ __align__(16) float    g_Bt [HH * HH];      // W1[:, H:]^T  (k-major)
__device__ __align__(16) float    g_ws [UU * HH];      // raw scatter sum: sum_i e_i * u_i
__device__ __align__(16) float    g_D  [UU * HH];      // (ws @ Bt)/denom + b1
__device__ __align__(16) float    g_sim[NN];           // similarity per row
__device__ __align__(16) unsigned g_smax[UU];          // encoded segment max
__device__ __align__(16) float    g_denom[UU];         // segment exp sum

// ---------------- helpers ------------------------------------------------------
__device__ __forceinline__ unsigned fenc(float f) {
    unsigned u = __float_as_uint(f);
    return (u & 0x80000000u) ? ~u : (u | 0x80000000u);
}
__device__ __forceinline__ float fdec(unsigned u) {
    return (u & 0x80000000u) ? __uint_as_float(u & 0x7FFFFFFFu) : __uint_as_float(~u);
}
__device__ __forceinline__ unsigned long long pack2(float f) {
    unsigned long long r;
    asm("mov.b64 %0, {%1, %1};" : "=l"(r) : "r"(__float_as_uint(f)));
    return r;
}
__device__ __forceinline__ float2 unpk(unsigned long long v) {
    float2 r;
    asm("mov.b64 {%0, %1}, %2;" : "=f"(r.x), "=f"(r.y) : "l"(v));
    return r;
}
__device__ __forceinline__ void fma2(unsigned long long& d, unsigned long long a, unsigned long long b) {
    asm("fma.rn.f32x2 %0, %1, %2, %0;" : "+l"(d) : "l"(a), "l"(b));
}

// ---------------- init scratch -------------------------------------------------
__global__ void k_zero() {
    int idx = blockIdx.x * 256 + threadIdx.x;      // grid 20000 blocks -> UU*HH threads
    g_ws[idx] = 0.0f;
    if (idx < UU) { g_denom[idx] = 0.0f; g_smax[idx] = 0u; }
}

// ---------------- tiny precompute GEMMs ---------------------------------------
// y==0: M[a,b]  = sum_j Wq[a,j]*Wk[b,j]
// y==1: C1[a,j] = sum_b Wv[a,b]*W1[j*512+b]
// y==2: Bt[a*256+j] = W1[j*512+256+a]
__global__ void k_prep(const float* __restrict__ Wq, const float* __restrict__ Wk,
                       const float* __restrict__ Wv, const float* __restrict__ W1) {
    int a = blockIdx.x, t = threadIdx.x;
    if (blockIdx.y == 2) {
        g_Bt[a * 256 + t] = W1[t * 512 + 256 + a];
        return;
    }
    __shared__ float rowS[256];
    const float* R = (blockIdx.y == 0) ? Wq : Wv;
    rowS[t] = R[a * 256 + t];
    __syncthreads();
    float acc = 0.0f;
    if (blockIdx.y == 0) {
        #pragma unroll 8
        for (int j = 0; j < 256; j++) acc += rowS[j] * Wk[t * 256 + j];
        g_M[a * 256 + t] = acc;
    } else {
        #pragma unroll 8
        for (int j = 0; j < 256; j++) acc += rowS[j] * W1[t * 512 + j];
        g_C1[a * 256 + t] = acc;
    }
}

// ---------------- main tiled GEMM (BM=64, BN=256, BK=32), f32x2 FMAs ----------
// MODE 0: T = A @ g_M ; sim = rowsum(T .* sess); store g_sim; atomicMax seg max
// MODE 1: g_D = (g_ws @ g_Bt) / denom + b1      (extra = b1)
// MODE 2: out = relu(A @ g_C1 + g_D[ids])
template<int MODE>
__global__ __launch_bounds__(256, 2)
void k_gemm(const float* __restrict__ A, const float* __restrict__ extra,
            const int* __restrict__ ids, float* __restrict__ outp, int nrows) {
    __shared__ __align__(16) float Us[64 * 33];
    __shared__ __align__(16) float Ms[32 * 256];

    const float* Ap = (MODE == 1) ? g_ws : A;
    const float* Bp = (MODE == 0) ? g_M : ((MODE == 1) ? g_Bt : g_C1);

    int tid = threadIdx.x;
    int tx = tid & 15, ty = tid >> 4;
    int rowBase = blockIdx.x * 64;

    unsigned long long acc[4][8];
    #pragma unroll
    for (int r = 0; r < 4; r++)
        #pragma unroll
        for (int c = 0; c < 8; c++) acc[r][c] = 0ull;

    for (int kt = 0; kt < 256; kt += 32) {
        // U tile: 64 x 32
        #pragma unroll
        for (int l = 0; l < 2; l++) {
            int f = tid + l * 256;
            int r = f >> 3;
            int c = (f & 7) * 4;
            int gr = rowBase + r;
            float4 v = (gr < nrows) ? *(const float4*)&Ap[(size_t)gr * 256 + kt + c]
                                    : make_float4(0.f, 0.f, 0.f, 0.f);
            float* d = &Us[r * 33 + c];
            d[0] = v.x; d[1] = v.y; d[2] = v.z; d[3] = v.w;
        }
        // M tile: 32 x 256
        #pragma unroll
        for (int l = 0; l < 8; l++) {
            int f = tid + l * 256;
            int r = f >> 6;
            int c = (f & 63) * 4;
            *(float4*)&Ms[r * 256 + c] = *(const float4*)&Bp[(kt + r) * 256 + c];
        }
        __syncthreads();

        #pragma unroll
        for (int k = 0; k < 32; k++) {
            unsigned long long u2[4];
            #pragma unroll
            for (int r = 0; r < 4; r++) u2[r] = pack2(Us[(ty * 4 + r) * 33 + k]);
            #pragma unroll
            for (int cc = 0; cc < 4; cc++) {
                const ulonglong2 m = *(const ulonglong2*)&Ms[k * 256 + cc * 64 + tx * 4];
                #pragma unroll
                for (int r = 0; r < 4; r++) {
                    fma2(acc[r][cc * 2 + 0], u2[r], m.x);
                    fma2(acc[r][cc * 2 + 1], u2[r], m.y);
                }
            }
        }
        __syncthreads();
    }

    // ------------- epilogues -------------
    if (MODE == 0) {
        #pragma unroll
        for (int r = 0; r < 4; r++) {
            int row = rowBase + ty * 4 + r;
            float part = 0.0f;
            #pragma unroll
            for (int cc = 0; cc < 4; cc++) {
                float4 s4 = *(const float4*)&extra[(size_t)row * 256 + cc * 64 + tx * 4];
                float2 p0 = unpk(acc[r][cc * 2 + 0]);
                float2 p1 = unpk(acc[r][cc * 2 + 1]);
                part += p0.x * s4.x + p0.y * s4.y + p1.x * s4.z + p1.y * s4.w;
            }
            #pragma unroll
            for (int o = 8; o; o >>= 1) part += __shfl_down_sync(0xffffffffu, part, o, 16);
            if (tx == 0) {
                g_sim[row] = part;
                atomicMax(&g_smax[ids[row]], fenc(part));
            }
        }
    } else if (MODE == 1) {
        #pragma unroll
        for (int r = 0; r < 4; r++) {
            int row = rowBase + ty * 4 + r;
            if (row >= nrows) continue;
            float inv = 1.0f / g_denom[row];
            #pragma unroll
            for (int cc = 0; cc < 4; cc++) {
                int col = cc * 64 + tx * 4;
                float4 b4 = *(const float4*)&extra[col];
                float2 p0 = unpk(acc[r][cc * 2 + 0]);
                float2 p1 = unpk(acc[r][cc * 2 + 1]);
                float4 o;
                o.x = p0.x * inv + b4.x;
                o.y = p0.y * inv + b4.y;
                o.z = p1.x * inv + b4.z;
                o.w = p1.y * inv + b4.w;
                *(float4*)&g_D[(size_t)row * 256 + col] = o;
            }
        }
    } else {  // MODE 2
        #pragma unroll
        for (int r = 0; r < 4; r++) {
            int row = rowBase + ty * 4 + r;
            int uid = ids[row];
            const float* Dr = g_D + (size_t)uid * 256;
            #pragma unroll
            for (int cc = 0; cc < 4; cc++) {
                int col = cc * 64 + tx * 4;
                float4 d4 = *(const float4*)&Dr[col];
                float2 p0 = unpk(acc[r][cc * 2 + 0]);
                float2 p1 = unpk(acc[r][cc * 2 + 1]);
                float4 o;
                o.x = fmaxf(p0.x + d4.x, 0.0f);
                o.y = fmaxf(p0.y + d4.y, 0.0f);
                o.z = fmaxf(p1.x + d4.z, 0.0f);
                o.w = fmaxf(p1.y + d4.w, 0.0f);
                *(float4*)&outp[(size_t)row * 256 + col] = o;
            }
        }
    }
}

// ---------------- exp + scatter (e_i, denom, ws) -------------------------------
// 4 rows per block, 64 lanes per row, each lane reduces a float4 via red.global.v4
__global__ void k_scatter(const float* __restrict__ ue, const int* __restrict__ ids) {
    int i    = blockIdx.x * 4 + (threadIdx.x >> 6);
    int lane = threadIdx.x & 63;
    int uid  = ids[i];
    float mx = fdec(g_smax[uid]);
    float e  = expf(g_sim[i] - mx);
    if (lane == 0) atomicAdd(&g_denom[uid], e);
    float4 u4 = *(const float4*)&ue[(size_t)i * 256 + lane * 4];
    float* p = &g_ws[(size_t)uid * 256 + lane * 4];
    asm volatile("red.global.add.v4.f32 [%0], {%1, %2, %3, %4};"
                 :: "l"(p), "f"(u4.x * e), "f"(u4.y * e), "f"(u4.z * e), "f"(u4.w * e)
                 : "memory");
}

// ---------------- launch --------------------------------------------------------
extern "C" void kernel_launch(void* const* d_in, const int* in_sizes, int n_in,
                              void* d_out, int out_size) {
    const float* sess = (const float*)d_in[0];
    const float* ue   = (const float*)d_in[1];
    const int*   ids  = (const int*)d_in[2];   // JAX x64 disabled: int64 request -> int32
    const float* Wq   = (const float*)d_in[3];
    const float* Wk   = (const float*)d_in[4];
    const float* Wv   = (const float*)d_in[5];
    const float* W1   = (const float*)d_in[6];
    const float* b1   = (const float*)d_in[7];
    float*       out  = (float*)d_out;
    int N = in_sizes[0] / HH;   // 200000

    k_zero<<<UU * HH / 256, 256>>>();
    dim3 gp(HH, 3);
    k_prep<<<gp, 256>>>(Wq, Wk, Wv, W1);
    // sim = rowsum((ue @ M) .* sess), segment max
    k_gemm<0><<<N / 64, 256>>>(ue, sess, ids, nullptr, N);
    // exp, denom, weighted scatter
    k_scatter<<<N / 4, 256>>>(ue, ids);
    // D = (ws @ Bt)/denom + b1
    k_gemm<1><<<(UU + 63) / 64, 256>>>(nullptr, b1, nullptr, nullptr, UU);
    // out = relu(ue @ C1 + D[ids])
    k_gemm<2><<<N / 64, 256>>>(ue, nullptr, ids, out, N);
}

// round 3
// speedup vs baseline: 1.3636x; 1.3636x over previous
#include <cuda_runtime.h>
#include <cuda_bf16.h>
#include <cstdint>

#define NN 200000
#define UU 20000
#define HH 256

#define BM 128
#define BN 256
#define BK 32
#define KS 40                 // padded k-stride in bf16 elems (80 bytes)
#define STAGE_BYTES 61440
#define AH_OFF 0
#define AL_OFF 10240
#define BH_OFF 20480
#define BL_OFF 40960

// ---------------- scratch (device globals) -------------------------------------
__device__ __align__(16) __nv_bfloat16 g_Ah[(size_t)NN * HH];
__device__ __align__(16) __nv_bfloat16 g_Al[(size_t)NN * HH];
__device__ __align__(16) __nv_bfloat16 g_Mth [HH * HH], g_Mtl [HH * HH];  // M^T  hi/lo (n-major)
__device__ __align__(16) __nv_bfloat16 g_C1th[HH * HH], g_C1tl[HH * HH];  // C1^T hi/lo (n-major)
__device__ __align__(16) float    g_Bt [HH * HH];      // W1[:,H:]^T (k-major, fp32)
__device__ __align__(16) float    g_ws [UU * HH];
__device__ __align__(16) float    g_D  [UU * HH];
__device__ __align__(16) float    g_sim[NN];
__device__ __align__(16) unsigned g_smax[UU];
__device__ __align__(16) float    g_denom[UU];

// ---------------- helpers -------------------------------------------------------
__device__ __forceinline__ unsigned fenc(float f) {
    unsigned u = __float_as_uint(f);
    return (u & 0x80000000u) ? ~u : (u | 0x80000000u);
}
__device__ __forceinline__ float fdec(unsigned u) {
    return (u & 0x80000000u) ? __uint_as_float(u & 0x7FFFFFFFu) : __uint_as_float(~u);
}
__device__ __forceinline__ unsigned long long pack2(float f) {
    unsigned long long r;
    asm("mov.b64 %0, {%1, %1};" : "=l"(r) : "r"(__float_as_uint(f)));
    return r;
}
__device__ __forceinline__ float2 unpk(unsigned long long v) {
    float2 r;
    asm("mov.b64 {%0, %1}, %2;" : "=f"(r.x), "=f"(r.y) : "l"(v));
    return r;
}
__device__ __forceinline__ void fma2(unsigned long long& d, unsigned long long a, unsigned long long b) {
    asm("fma.rn.f32x2 %0, %1, %2, %0;" : "+l"(d) : "l"(a), "l"(b));
}
__device__ __forceinline__ void ldsm4(uint32_t* r, uint32_t addr) {
    asm volatile("ldmatrix.sync.aligned.m8n8.x4.shared.b16 {%0,%1,%2,%3}, [%4];"
                 : "=r"(r[0]), "=r"(r[1]), "=r"(r[2]), "=r"(r[3]) : "r"(addr));
}
__device__ __forceinline__ void mma16816(float* c, const uint32_t* a, const uint32_t* b) {
    asm volatile("mma.sync.aligned.m16n8k16.row.col.f32.bf16.bf16.f32 "
                 "{%0,%1,%2,%3}, {%4,%5,%6,%7}, {%8,%9}, {%0,%1,%2,%3};"
                 : "+f"(c[0]), "+f"(c[1]), "+f"(c[2]), "+f"(c[3])
                 : "r"(a[0]), "r"(a[1]), "r"(a[2]), "r"(a[3]), "r"(b[0]), "r"(b[1]));
}
__device__ __forceinline__ void cpa16(uint32_t dst, const void* src, bool v) {
    int sz = v ? 16 : 0;
    asm volatile("cp.async.cg.shared.global [%0], [%1], 16, %2;"
                 :: "r"(dst), "l"(src), "r"(sz));
}

// ---------------- init scratch -------------------------------------------------
__global__ void k_zero() {
    int idx = blockIdx.x * 256 + threadIdx.x;   // 20000 blocks -> UU*HH
    g_ws[idx] = 0.0f;
    if (idx < UU) { g_denom[idx] = 0.0f; g_smax[idx] = 0u; }
}

// ---------------- precompute ----------------------------------------------------
// y==0: M[a,t]  = sum_j Wq[a,j]*Wk[t,j]      -> g_Mth/l [t*256+a]  (transposed)
// y==1: C1[a,t] = sum_j Wv[a,j]*W1[t*512+j]  -> g_C1th/l[t*256+a]
// y==2: Bt[a*256+t] = W1[t*512+256+a]
__global__ void k_prep(const float* __restrict__ Wq, const float* __restrict__ Wk,
                       const float* __restrict__ Wv, const float* __restrict__ W1) {
    int a = blockIdx.x, t = threadIdx.x;
    if (blockIdx.y == 2) {
        g_Bt[a * 256 + t] = W1[t * 512 + 256 + a];
        return;
    }
    __shared__ float rowS[256];
    const float* R = (blockIdx.y == 0) ? Wq : Wv;
    rowS[t] = R[a * 256 + t];
    __syncthreads();
    float acc = 0.0f;
    if (blockIdx.y == 0) {
        #pragma unroll 8
        for (int j = 0; j < 256; j++) acc += rowS[j] * Wk[t * 256 + j];
    } else {
        #pragma unroll 8
        for (int j = 0; j < 256; j++) acc += rowS[j] * W1[t * 512 + j];
    }
    __nv_bfloat16 h = __float2bfloat16(acc);
    __nv_bfloat16 l = __float2bfloat16(acc - __bfloat162float(h));
    if (blockIdx.y == 0) { g_Mth [t * 256 + a] = h; g_Mtl [t * 256 + a] = l; }
    else                 { g_C1th[t * 256 + a] = h; g_C1tl[t * 256 + a] = l; }
}

// ---------------- ue -> bf16 hi/lo ----------------------------------------------
__global__ void k_cvtA(const float4* __restrict__ ue) {
    size_t i = (size_t)blockIdx.x * 256 + threadIdx.x;   // NN*HH/4 threads
    float4 v = ue[i];
    __nv_bfloat16 h0 = __float2bfloat16(v.x), h1 = __float2bfloat16(v.y);
    __nv_bfloat16 h2 = __float2bfloat16(v.z), h3 = __float2bfloat16(v.w);
    __nv_bfloat162* Ah2 = (__nv_bfloat162*)g_Ah;
    Ah2[i * 2 + 0] = __halves2bfloat162(h0, h1);
    Ah2[i * 2 + 1] = __halves2bfloat162(h2, h3);
    __nv_bfloat16 l0 = __float2bfloat16(v.x - __bfloat162float(h0));
    __nv_bfloat16 l1 = __float2bfloat16(v.y - __bfloat162float(h1));
    __nv_bfloat16 l2 = __float2bfloat16(v.z - __bfloat162float(h2));
    __nv_bfloat16 l3 = __float2bfloat16(v.w - __bfloat162float(h3));
    __nv_bfloat162* Al2 = (__nv_bfloat162*)g_Al;
    Al2[i * 2 + 0] = __halves2bfloat162(l0, l1);
    Al2[i * 2 + 1] = __halves2bfloat162(l2, l3);
}

// ---------------- tensor-core GEMM (split-bf16, 3 MMAs) -------------------------
// MODE 0: sim = rowsum((ue @ M) .* sess); g_sim; segment atomicMax
// MODE 2: out = relu(ue @ C1 + g_D[ids])
template<int MODE>
__global__ __launch_bounds__(512, 1)
void k_mma(const float* __restrict__ sess, const int* __restrict__ ids,
           float* __restrict__ outp, int nrows) {
    extern __shared__ __align__(16) char smem[];
    uint32_t sbase = (uint32_t)__cvta_generic_to_shared(smem);
    const int tid  = threadIdx.x;
    const int lane = tid & 31;
    const int wid  = tid >> 5;
    const int mw = wid >> 2, nw = wid & 3;
    const int blockRow = blockIdx.x * BM;

    const __nv_bfloat16* Bth = (MODE == 0) ? g_Mth : g_C1th;
    const __nv_bfloat16* Btl = (MODE == 0) ? g_Mtl : g_C1tl;

    float acc[2][8][4];
    #pragma unroll
    for (int t = 0; t < 2; t++)
        #pragma unroll
        for (int j = 0; j < 8; j++)
            #pragma unroll
            for (int c = 0; c < 4; c++) acc[t][j][c] = 0.0f;

    // ---- async tile loader (stage s, k-tile kt) ----
    auto load_stage = [&](int kt, int s) {
        uint32_t db = sbase + (uint32_t)s * STAGE_BYTES;
        {   // A hi/lo: 128 rows x 32 bf16 = 512 chunks of 16B each
            int r = tid >> 2, ch = tid & 3;
            int grow = blockRow + r;
            bool v = grow < nrows;
            size_t gi = (size_t)(v ? grow : 0) * HH + kt * BK + ch * 8;
            cpa16(db + AH_OFF + r * 80 + ch * 16, g_Ah + gi, v);
            cpa16(db + AL_OFF + r * 80 + ch * 16, g_Al + gi, v);
        }
        #pragma unroll
        for (int i = 0; i < 2; i++) {   // B hi/lo: 256 rows x 32 bf16
            int c = tid * 2 + i;
            int r = c >> 2, ch = c & 3;
            size_t gi = (size_t)r * HH + kt * BK + ch * 8;
            cpa16(db + BH_OFF + r * 80 + ch * 16, Bth + gi, true);
            cpa16(db + BL_OFF + r * 80 + ch * 16, Btl + gi, true);
        }
        asm volatile("cp.async.commit_group;" ::: "memory");
    };

    load_stage(0, 0);

    for (int kt = 0; kt < HH / BK; kt++) {
        if (kt + 1 < HH / BK) {
            load_stage(kt + 1, (kt + 1) & 1);
            asm volatile("cp.async.wait_group 1;" ::: "memory");
        } else {
            asm volatile("cp.async.wait_group 0;" ::: "memory");
        }
        __syncthreads();
        uint32_t sb = sbase + (uint32_t)(kt & 1) * STAGE_BYTES;
        #pragma unroll
        for (int k16 = 0; k16 < BK; k16 += 16) {
            uint32_t ah[2][4], al[2][4];
            #pragma unroll
            for (int t = 0; t < 2; t++) {
                uint32_t ao = (uint32_t)(((mw * 32 + t * 16 + (lane & 15)) * KS
                                          + k16 + ((lane >> 4) << 3)) * 2);
                ldsm4(ah[t], sb + AH_OFF + ao);
                ldsm4(al[t], sb + AL_OFF + ao);
            }
            #pragma unroll
            for (int p = 0; p < 4; p++) {
                uint32_t bo = (uint32_t)(((nw * 64 + p * 16 + (lane & 7) + ((lane >> 4) << 3)) * KS
                                          + k16 + (lane & 8)) * 2);
                uint32_t bh[4], bl[4];
                ldsm4(bh, sb + BH_OFF + bo);
                ldsm4(bl, sb + BL_OFF + bo);
                #pragma unroll
                for (int t = 0; t < 2; t++)
                    #pragma unroll
                    for (int q = 0; q < 2; q++) {
                        int j = p * 2 + q;
                        mma16816(acc[t][j], ah[t], &bh[2 * q]);
                        mma16816(acc[t][j], ah[t], &bl[2 * q]);
                        mma16816(acc[t][j], al[t], &bh[2 * q]);
                    }
            }
        }
        __syncthreads();
    }

    const int lr = lane >> 2;           // 0..7
    const int lc = (lane & 3) * 2;      // 0,2,4,6

    if (MODE == 0) {
        float part[2][2] = {{0.f, 0.f}, {0.f, 0.f}};
        #pragma unroll
        for (int t = 0; t < 2; t++) {
            int row0 = blockRow + mw * 32 + t * 16 + lr;
            #pragma unroll
            for (int j = 0; j < 8; j++) {
                int col = nw * 64 + j * 8 + lc;
                if (row0 < nrows) {
                    float2 s = *(const float2*)&sess[(size_t)row0 * 256 + col];
                    part[t][0] += acc[t][j][0] * s.x + acc[t][j][1] * s.y;
                }
                if (row0 + 8 < nrows) {
                    float2 s = *(const float2*)&sess[(size_t)(row0 + 8) * 256 + col];
                    part[t][1] += acc[t][j][2] * s.x + acc[t][j][3] * s.y;
                }
            }
        }
        #pragma unroll
        for (int t = 0; t < 2; t++)
            #pragma unroll
            for (int h = 0; h < 2; h++) {
                part[t][h] += __shfl_xor_sync(0xffffffffu, part[t][h], 1);
                part[t][h] += __shfl_xor_sync(0xffffffffu, part[t][h], 2);
            }
        float* red = (float*)smem;      // [128][4]
        if ((lane & 3) == 0) {
            #pragma unroll
            for (int t = 0; t < 2; t++) {
                red[(mw * 32 + t * 16 + lr) * 4 + nw]     = part[t][0];
                red[(mw * 32 + t * 16 + lr + 8) * 4 + nw] = part[t][1];
            }
        }
        __syncthreads();
        if (tid < 128) {
            int row = blockRow + tid;
            if (row < nrows) {
                float s = red[tid * 4] + red[tid * 4 + 1] + red[tid * 4 + 2] + red[tid * 4 + 3];
                g_sim[row] = s;
                atomicMax(&g_smax[ids[row]], fenc(s));
            }
        }
    } else {
        #pragma unroll
        for (int t = 0; t < 2; t++)
            #pragma unroll
            for (int h = 0; h < 2; h++) {
                int row = blockRow + mw * 32 + t * 16 + lr + h * 8;
                if (row >= nrows) continue;
                int uid = ids[row];
                const float* Dr = g_D + (size_t)uid * 256;
                #pragma unroll
                for (int j = 0; j < 8; j++) {
                    int col = nw * 64 + j * 8 + lc;
                    float2 d = *(const float2*)&Dr[col];
                    float2 o;
                    o.x = fmaxf(acc[t][j][2 * h + 0] + d.x, 0.0f);
                    o.y = fmaxf(acc[t][j][2 * h + 1] + d.y, 0.0f);
                    *(float2*)&outp[(size_t)row * 256 + col] = o;
                }
            }
    }
}

// ---------------- fp32 U-level GEMM: g_D = (g_ws @ g_Bt)/denom + b1 -------------
__global__ __launch_bounds__(256, 2)
void k_gemmU(const float* __restrict__ b1) {
    __shared__ __align__(16) float Us[64 * 33];
    __shared__ __align__(16) float Ms[32 * 256];
    int tid = threadIdx.x;
    int tx = tid & 15, ty = tid >> 4;
    int rowBase = blockIdx.x * 64;

    unsigned long long acc[4][8];
    #pragma unroll
    for (int r = 0; r < 4; r++)
        #pragma unroll
        for (int c = 0; c < 8; c++) acc[r][c] = 0ull;

    for (int kt = 0; kt < 256; kt += 32) {
        #pragma unroll
        for (int l = 0; l < 2; l++) {
            int f = tid + l * 256;
            int r = f >> 3, c = (f & 7) * 4;
            int gr = rowBase + r;
            float4 v = (gr < UU) ? *(const float4*)&g_ws[(size_t)gr * 256 + kt + c]
                                 : make_float4(0.f, 0.f, 0.f, 0.f);
            float* d = &Us[r * 33 + c];
            d[0] = v.x; d[1] = v.y; d[2] = v.z; d[3] = v.w;
        }
        #pragma unroll
        for (int l = 0; l < 8; l++) {
            int f = tid + l * 256;
            int r = f >> 6, c = (f & 63) * 4;
            *(float4*)&Ms[r * 256 + c] = *(const float4*)&g_Bt[(kt + r) * 256 + c];
        }
        __syncthreads();
        #pragma unroll
        for (int k = 0; k < 32; k++) {
            unsigned long long u2[4];
            #pragma unroll
            for (int r = 0; r < 4; r++) u2[r] = pack2(Us[(ty * 4 + r) * 33 + k]);
            #pragma unroll
            for (int cc = 0; cc < 4; cc++) {
                const ulonglong2 m = *(const ulonglong2*)&Ms[k * 256 + cc * 64 + tx * 4];
                #pragma unroll
                for (int r = 0; r < 4; r++) {
                    fma2(acc[r][cc * 2 + 0], u2[r], m.x);
                    fma2(acc[r][cc * 2 + 1], u2[r], m.y);
                }
            }
        }
        __syncthreads();
    }
    #pragma unroll
    for (int r = 0; r < 4; r++) {
        int row = rowBase + ty * 4 + r;
        if (row >= UU) continue;
        float inv = 1.0f / g_denom[row];
        #pragma unroll
        for (int cc = 0; cc < 4; cc++) {
            int col = cc * 64 + tx * 4;
            float4 b4 = *(const float4*)&b1[col];
            float2 p0 = unpk(acc[r][cc * 2 + 0]);
            float2 p1 = unpk(acc[r][cc * 2 + 1]);
            float4 o;
            o.x = p0.x * inv + b4.x;
            o.y = p0.y * inv + b4.y;
            o.z = p1.x * inv + b4.z;
            o.w = p1.y * inv + b4.w;
            *(float4*)&g_D[(size_t)row * 256 + col] = o;
        }
    }
}

// ---------------- exp + scatter --------------------------------------------------
__global__ void k_scatter(const float* __restrict__ ue, const int* __restrict__ ids) {
    int i    = blockIdx.x * 4 + (threadIdx.x >> 6);
    int lane = threadIdx.x & 63;
    int uid  = ids[i];
    float mx = fdec(g_smax[uid]);
    float e  = expf(g_sim[i] - mx);
    if (lane == 0) atomicAdd(&g_denom[uid], e);
    float4 u4 = *(const float4*)&ue[(size_t)i * 256 + lane * 4];
    float* p = &g_ws[(size_t)uid * 256 + lane * 4];
    asm volatile("red.global.add.v4.f32 [%0], {%1, %2, %3, %4};"
                 :: "l"(p), "f"(u4.x * e), "f"(u4.y * e), "f"(u4.z * e), "f"(u4.w * e)
                 : "memory");
}

// ---------------- launch ----------------------------------------------------------
extern "C" void kernel_launch(void* const* d_in, const int* in_sizes, int n_in,
                              void* d_out, int out_size) {
    const float* sess = (const float*)d_in[0];
    const float* ue   = (const float*)d_in[1];
    const int*   ids  = (const int*)d_in[2];   // JAX x64 disabled: int32
    const float* Wq   = (const float*)d_in[3];
    const float* Wk   = (const float*)d_in[4];
    const float* Wv   = (const float*)d_in[5];
    const float* W1   = (const float*)d_in[6];
    const float* b1   = (const float*)d_in[7];
    float*       out  = (float*)d_out;
    int N = in_sizes[0] / HH;   // 200000

    static bool attr_set = false;
    if (!attr_set) {
        cudaFuncSetAttribute(k_mma<0>, cudaFuncAttributeMaxDynamicSharedMemorySize, 2 * STAGE_BYTES);
        cudaFuncSetAttribute(k_mma<2>, cudaFuncAttributeMaxDynamicSharedMemorySize, 2 * STAGE_BYTES);
        attr_set = true;
    }

    int nblk = (N + BM - 1) / BM;
    k_zero<<<UU * HH / 256, 256>>>();
    dim3 gp(HH, 3);
    k_prep<<<gp, 256>>>(Wq, Wk, Wv, W1);
    k_cvtA<<<N * (HH / 4) / 256, 256>>>((const float4*)ue);
    k_mma<0><<<nblk, 512, 2 * STAGE_BYTES>>>(sess, ids, nullptr, N);
    k_scatter<<<N / 4, 256>>>(ue, ids);
    k_gemmU<<<(UU + 63) / 64, 256>>>(b1);
    k_mma<2><<<nblk, 512, 2 * STAGE_BYTES>>>(nullptr, ids, out, N);
}

// round 5
// speedup vs baseline: 1.5953x; 1.1699x over previous
#include <cuda_runtime.h>
#include <cuda_bf16.h>
#include <cstdint>

#define NN 200000
#define UU 20000
#define HH 256

#define BM 128
#define BN 256
#define BK 32
#define KS 40                 // padded k-stride in bf16 elems (80 bytes)
#define STAGE_BYTES 61440
#define AH_OFF 0
#define AL_OFF 10240
#define BH_OFF 20480
#define BL_OFF 40960

// ---------------- scratch (device globals) -------------------------------------
__device__ __align__(16) __nv_bfloat16 g_Ah[(size_t)NN * HH];
__device__ __align__(16) __nv_bfloat16 g_Al[(size_t)NN * HH];
__device__ __align__(16) __nv_bfloat16 g_Mth [HH * HH], g_Mtl [HH * HH];  // M^T  hi/lo (n-major)
__device__ __align__(16) __nv_bfloat16 g_C1th[HH * HH], g_C1tl[HH * HH];  // C1^T hi/lo
__device__ __align__(16) float    g_Bt [HH * HH];      // W1[:,H:]^T (k-major, fp32)
__device__ __align__(16) float    g_ws [UU * HH];
__device__ __align__(16) float    g_D  [UU * HH];
__device__ __align__(16) float    g_sim[NN];
__device__ __align__(16) unsigned g_smax[UU];
__device__ __align__(16) float    g_denom[UU];

// ---------------- helpers -------------------------------------------------------
__device__ __forceinline__ unsigned fenc(float f) {
    unsigned u = __float_as_uint(f);
    return (u & 0x80000000u) ? ~u : (u | 0x80000000u);
}
__device__ __forceinline__ float fdec(unsigned u) {
    return (u & 0x80000000u) ? __uint_as_float(u & 0x7FFFFFFFu) : __uint_as_float(~u);
}
__device__ __forceinline__ unsigned long long pack2(float f) {
    unsigned long long r;
    asm("mov.b64 %0, {%1, %1};" : "=l"(r) : "r"(__float_as_uint(f)));
    return r;
}
__device__ __forceinline__ float2 unpk(unsigned long long v) {
    float2 r;
    asm("mov.b64 {%0, %1}, %2;" : "=f"(r.x), "=f"(r.y) : "l"(v));
    return r;
}
__device__ __forceinline__ void fma2(unsigned long long& d, unsigned long long a, unsigned long long b) {
    asm("fma.rn.f32x2 %0, %1, %2, %0;" : "+l"(d) : "l"(a), "l"(b));
}
__device__ __forceinline__ void ldsm4(uint32_t* r, uint32_t addr) {
    asm volatile("ldmatrix.sync.aligned.m8n8.x4.shared.b16 {%0,%1,%2,%3}, [%4];"
                 : "=r"(r[0]), "=r"(r[1]), "=r"(r[2]), "=r"(r[3]) : "r"(addr));
}
__device__ __forceinline__ void mma16816(float* c, const uint32_t* a, const uint32_t* b) {
    asm volatile("mma.sync.aligned.m16n8k16.row.col.f32.bf16.bf16.f32 "
                 "{%0,%1,%2,%3}, {%4,%5,%6,%7}, {%8,%9}, {%0,%1,%2,%3};"
                 : "+f"(c[0]), "+f"(c[1]), "+f"(c[2]), "+f"(c[3])
                 : "r"(a[0]), "r"(a[1]), "r"(a[2]), "r"(a[3]), "r"(b[0]), "r"(b[1]));
}
__device__ __forceinline__ void cpa16(uint32_t dst, const void* src, bool v) {
    int sz = v ? 16 : 0;
    asm volatile("cp.async.cg.shared.global [%0], [%1], 16, %2;"
                 :: "r"(dst), "l"(src), "r"(sz));
}

// ---------------- init scratch -------------------------------------------------
__global__ void k_zero() {
    int idx = blockIdx.x * 256 + threadIdx.x;   // 20000 blocks -> UU*HH
    g_ws[idx] = 0.0f;
    if (idx < UU) { g_denom[idx] = 0.0f; g_smax[idx] = 0u; }
}

// ---------------- coalesced precompute GEMMs -----------------------------------
// z==0: M[a,t]  = Wq[a,:]·Wk[t,:]      -> g_Mth/l [t*256+a]
// z==1: C1[a,t] = Wv[a,:]·W1[t,0:256]  -> g_C1th/l[t*256+a]
__global__ void k_prepT(const float* __restrict__ Wq, const float* __restrict__ Wk,
                        const float* __restrict__ Wv, const float* __restrict__ W1) {
    __shared__ float As[32 * 129];
    __shared__ float Bs[32 * 129];
    int z = blockIdx.z;
    int tid = threadIdx.x;
    int abase = blockIdx.y * 32;
    int tbase = blockIdx.x * 32;
    const float* Ag = z ? Wv : Wq;
    int tx = tid & 31, ty = tid >> 5;
    float acc[4] = {0.f, 0.f, 0.f, 0.f};

    for (int kt = 0; kt < 256; kt += 128) {
        #pragma unroll
        for (int i = 0; i < 16; i++) {
            int f = tid + i * 256;
            int r = f >> 7, c = f & 127;
            As[r * 129 + c] = Ag[(abase + r) * 256 + kt + c];
            Bs[r * 129 + c] = z ? W1[(tbase + r) * 512 + kt + c]
                                : Wk[(tbase + r) * 256 + kt + c];
        }
        __syncthreads();
        #pragma unroll 4
        for (int k = 0; k < 128; k++) {
            float av = As[tx * 129 + k];
            #pragma unroll
            for (int j = 0; j < 4; j++) acc[j] += av * Bs[(ty + 8 * j) * 129 + k];
        }
        __syncthreads();
    }
    int a = abase + tx;
    #pragma unroll
    for (int j = 0; j < 4; j++) {
        int t = tbase + ty + 8 * j;
        __nv_bfloat16 h = __float2bfloat16(acc[j]);
        __nv_bfloat16 l = __float2bfloat16(acc[j] - __bfloat162float(h));
        if (z == 0) { g_Mth [t * 256 + a] = h; g_Mtl [t * 256 + a] = l; }
        else        { g_C1th[t * 256 + a] = h; g_C1tl[t * 256 + a] = l; }
    }
}

__global__ void k_prepBt(const float* __restrict__ W1) {
    int a = blockIdx.x, t = threadIdx.x;
    g_Bt[a * 256 + t] = W1[t * 512 + 256 + a];
}

// ---------------- ue -> bf16 hi/lo ----------------------------------------------
__global__ void k_cvtA(const float4* __restrict__ ue) {
    size_t i = (size_t)blockIdx.x * 256 + threadIdx.x;   // NN*HH/4 threads
    float4 v = ue[i];
    __nv_bfloat16 h0 = __float2bfloat16(v.x), h1 = __float2bfloat16(v.y);
    __nv_bfloat16 h2 = __float2bfloat16(v.z), h3 = __float2bfloat16(v.w);
    __nv_bfloat162* Ah2 = (__nv_bfloat162*)g_Ah;
    Ah2[i * 2 + 0] = __halves2bfloat162(h0, h1);
    Ah2[i * 2 + 1] = __halves2bfloat162(h2, h3);
    __nv_bfloat16 l0 = __float2bfloat16(v.x - __bfloat162float(h0));
    __nv_bfloat16 l1 = __float2bfloat16(v.y - __bfloat162float(h1));
    __nv_bfloat16 l2 = __float2bfloat16(v.z - __bfloat162float(h2));
    __nv_bfloat16 l3 = __float2bfloat16(v.w - __bfloat162float(h3));
    __nv_bfloat162* Al2 = (__nv_bfloat162*)g_Al;
    Al2[i * 2 + 0] = __halves2bfloat162(l0, l1);
    Al2[i * 2 + 1] = __halves2bfloat162(l2, l3);
}

// ---------------- tensor-core GEMM (split-bf16, 3 MMAs) -------------------------
// MODE 0: sim = rowsum((ue @ M) .* sess); g_sim; segment atomicMax
// MODE 2: out = relu(ue @ C1 + g_D[ids])
template<int MODE>
__global__ __launch_bounds__(512, 1)
void k_mma(const float* __restrict__ sess, const int* __restrict__ ids,
           float* __restrict__ outp, int nrows) {
    extern __shared__ __align__(16) char smem[];
    uint32_t sbase = (uint32_t)__cvta_generic_to_shared(smem);
    const int tid  = threadIdx.x;
    const int lane = tid & 31;
    const int wid  = tid >> 5;
    const int mw = wid >> 2, nw = wid & 3;
    const int blockRow = blockIdx.x * BM;

    const __nv_bfloat16* Bth = (MODE == 0) ? g_Mth : g_C1th;
    const __nv_bfloat16* Btl = (MODE == 0) ? g_Mtl : g_C1tl;

    float acc[2][8][4];
    #pragma unroll
    for (int t = 0; t < 2; t++)
        #pragma unroll
        for (int j = 0; j < 8; j++)
            #pragma unroll
            for (int c = 0; c < 4; c++) acc[t][j][c] = 0.0f;

    // ---- async tile loader (stage s, k-tile kt) ----
    auto load_stage = [&](int kt, int s) {
        uint32_t db = sbase + (uint32_t)s * STAGE_BYTES;
        {   // A hi/lo: 128 rows x 32 bf16 = 512 chunks of 16B each
            int r = tid >> 2, ch = tid & 3;
            int grow = blockRow + r;
            bool v = grow < nrows;
            size_t gi = (size_t)(v ? grow : 0) * HH + kt * BK + ch * 8;
            cpa16(db + AH_OFF + r * 80 + ch * 16, g_Ah + gi, v);
            cpa16(db + AL_OFF + r * 80 + ch * 16, g_Al + gi, v);
        }
        #pragma unroll
        for (int i = 0; i < 2; i++) {   // B hi/lo: 256 rows x 32 bf16
            int c = tid * 2 + i;
            int r = c >> 2, ch = c & 3;
            size_t gi = (size_t)r * HH + kt * BK + ch * 8;
            cpa16(db + BH_OFF + r * 80 + ch * 16, Bth + gi, true);
            cpa16(db + BL_OFF + r * 80 + ch * 16, Btl + gi, true);
        }
        asm volatile("cp.async.commit_group;" ::: "memory");
    };

    load_stage(0, 0);

    for (int kt = 0; kt < HH / BK; kt++) {
        if (kt + 1 < HH / BK) {
            load_stage(kt + 1, (kt + 1) & 1);
            asm volatile("cp.async.wait_group 1;" ::: "memory");
        } else {
            asm volatile("cp.async.wait_group 0;" ::: "memory");
        }
        __syncthreads();
        uint32_t sb = sbase + (uint32_t)(kt & 1) * STAGE_BYTES;
        #pragma unroll
        for (int k16 = 0; k16 < BK; k16 += 16) {
            uint32_t ah[2][4], al[2][4];
            #pragma unroll
            for (int t = 0; t < 2; t++) {
                uint32_t ao = (uint32_t)(((mw * 32 + t * 16 + (lane & 15)) * KS
                                          + k16 + ((lane >> 4) << 3)) * 2);
                ldsm4(ah[t], sb + AH_OFF + ao);
                ldsm4(al[t], sb + AL_OFF + ao);
            }
            #pragma unroll
            for (int p = 0; p < 4; p++) {
                uint32_t bo = (uint32_t)(((nw * 64 + p * 16 + (lane & 7) + ((lane >> 4) << 3)) * KS
                                          + k16 + (lane & 8)) * 2);
                uint32_t bh[4], bl[4];
                ldsm4(bh, sb + BH_OFF + bo);
                ldsm4(bl, sb + BL_OFF + bo);
                // three sweeps over the 4 independent accumulators (reuse distance 4)
                #pragma unroll
                for (int t = 0; t < 2; t++)
                    #pragma unroll
                    for (int q = 0; q < 2; q++)
                        mma16816(acc[t][p * 2 + q], ah[t], &bh[2 * q]);
                #pragma unroll
                for (int t = 0; t < 2; t++)
                    #pragma unroll
                    for (int q = 0; q < 2; q++)
                        mma16816(acc[t][p * 2 + q], ah[t], &bl[2 * q]);
                #pragma unroll
                for (int t = 0; t < 2; t++)
                    #pragma unroll
                    for (int q = 0; q < 2; q++)
                        mma16816(acc[t][p * 2 + q], al[t], &bh[2 * q]);
            }
        }
        __syncthreads();
    }

    const int lr = lane >> 2;           // 0..7
    const int lc = (lane & 3) * 2;      // 0,2,4,6

    if (MODE == 0) {
        float part[2][2] = {{0.f, 0.f}, {0.f, 0.f}};
        #pragma unroll
        for (int t = 0; t < 2; t++) {
            int row0 = blockRow + mw * 32 + t * 16 + lr;
            #pragma unroll
            for (int j = 0; j < 8; j++) {
                int col = nw * 64 + j * 8 + lc;
                if (row0 < nrows) {
                    float2 s = *(const float2*)&sess[(size_t)row0 * 256 + col];
                    part[t][0] += acc[t][j][0] * s.x + acc[t][j][1] * s.y;
                }
                if (row0 + 8 < nrows) {
                    float2 s = *(const float2*)&sess[(size_t)(row0 + 8) * 256 + col];
                    part[t][1] += acc[t][j][2] * s.x + acc[t][j][3] * s.y;
                }
            }
        }
        #pragma unroll
        for (int t = 0; t < 2; t++)
            #pragma unroll
            for (int h = 0; h < 2; h++) {
                part[t][h] += __shfl_xor_sync(0xffffffffu, part[t][h], 1);
                part[t][h] += __shfl_xor_sync(0xffffffffu, part[t][h], 2);
            }
        float* red = (float*)smem;      // [128][4]
        if ((lane & 3) == 0) {
            #pragma unroll
            for (int t = 0; t < 2; t++) {
                red[(mw * 32 + t * 16 + lr) * 4 + nw]     = part[t][0];
                red[(mw * 32 + t * 16 + lr + 8) * 4 + nw] = part[t][1];
            }
        }
        __syncthreads();
        if (tid < 128) {
            int row = blockRow + tid;
            if (row < nrows) {
                float s = red[tid * 4] + red[tid * 4 + 1] + red[tid * 4 + 2] + red[tid * 4 + 3];
                g_sim[row] = s;
                atomicMax(&g_smax[ids[row]], fenc(s));
            }
        }
    } else {
        #pragma unroll
        for (int t = 0; t < 2; t++)
            #pragma unroll
            for (int h = 0; h < 2; h++) {
                int row = blockRow + mw * 32 + t * 16 + lr + h * 8;
                if (row >= nrows) continue;
                int uid = ids[row];
                const float* Dr = g_D + (size_t)uid * 256;
                #pragma unroll
                for (int j = 0; j < 8; j++) {
                    int col = nw * 64 + j * 8 + lc;
                    float2 d = *(const float2*)&Dr[col];
                    float2 o;
                    o.x = fmaxf(acc[t][j][2 * h + 0] + d.x, 0.0f);
                    o.y = fmaxf(acc[t][j][2 * h + 1] + d.y, 0.0f);
                    *(float2*)&outp[(size_t)row * 256 + col] = o;
                }
            }
    }
}

// ---------------- fp32 U-level GEMM: g_D = (g_ws @ g_Bt)/denom + b1 -------------
__global__ __launch_bounds__(256, 2)
void k_gemmU(const float* __restrict__ b1) {
    __shared__ __align__(16) float Us[64 * 33];
    __shared__ __align__(16) float Ms[32 * 256];
    int tid = threadIdx.x;
    int tx = tid & 15, ty = tid >> 4;
    int rowBase = blockIdx.x * 64;

    unsigned long long acc[4][8];
    #pragma unroll
    for (int r = 0; r < 4; r++)
        #pragma unroll
        for (int c = 0; c < 8; c++) acc[r][c] = 0ull;

    for (int kt = 0; kt < 256; kt += 32) {
        #pragma unroll
        for (int l = 0; l < 2; l++) {
            int f = tid + l * 256;
            int r = f >> 3, c = (f & 7) * 4;
            int gr = rowBase + r;
            float4 v = (gr < UU) ? *(const float4*)&g_ws[(size_t)gr * 256 + kt + c]
                                 : make_float4(0.f, 0.f, 0.f, 0.f);
            float* d = &Us[r * 33 + c];
            d[0] = v.x; d[1] = v.y; d[2] = v.z; d[3] = v.w;
        }
        #pragma unroll
        for (int l = 0; l < 8; l++) {
            int f = tid + l * 256;
            int r = f >> 6, c = (f & 63) * 4;
            *(float4*)&Ms[r * 256 + c] = *(const float4*)&g_Bt[(kt + r) * 256 + c];
        }
        __syncthreads();
        #pragma unroll
        for (int k = 0; k < 32; k++) {
            unsigned long long u2[4];
            #pragma unroll
            for (int r = 0; r < 4; r++) u2[r] = pack2(Us[(ty * 4 + r) * 33 + k]);
            #pragma unroll
            for (int cc = 0; cc < 4; cc++) {
                const ulonglong2 m = *(const ulonglong2*)&Ms[k * 256 + cc * 64 + tx * 4];
                #pragma unroll
                for (int r = 0; r < 4; r++) {
                    fma2(acc[r][cc * 2 + 0], u2[r], m.x);
                    fma2(acc[r][cc * 2 + 1], u2[r], m.y);
                }
            }
        }
        __syncthreads();
    }
    #pragma unroll
    for (int r = 0; r < 4; r++) {
        int row = rowBase + ty * 4 + r;
        if (row >= UU) continue;
        float inv = 1.0f / g_denom[row];
        #pragma unroll
        for (int cc = 0; cc < 4; cc++) {
            int col = cc * 64 + tx * 4;
            float4 b4 = *(const float4*)&b1[col];
            float2 p0 = unpk(acc[r][cc * 2 + 0]);
            float2 p1 = unpk(acc[r][cc * 2 + 1]);
            float4 o;
            o.x = p0.x * inv + b4.x;
            o.y = p0.y * inv + b4.y;
            o.z = p1.x * inv + b4.z;
            o.w = p1.y * inv + b4.w;
            *(float4*)&g_D[(size_t)row * 256 + col] = o;
        }
    }
}

// ---------------- exp + scatter --------------------------------------------------
__global__ void k_scatter(const float* __restrict__ ue, const int* __restrict__ ids) {
    int i    = blockIdx.x * 4 + (threadIdx.x >> 6);
    int lane = threadIdx.x & 63;
    int uid  = ids[i];
    float mx = fdec(g_smax[uid]);
    float e  = expf(g_sim[i] - mx);
    if (lane == 0) atomicAdd(&g_denom[uid], e);
    float4 u4 = *(const float4*)&ue[(size_t)i * 256 + lane * 4];
    float* p = &g_ws[(size_t)uid * 256 + lane * 4];
    asm volatile("red.global.add.v4.f32 [%0], {%1, %2, %3, %4};"
                 :: "l"(p), "f"(u4.x * e), "f"(u4.y * e), "f"(u4.z * e), "f"(u4.w * e)
                 : "memory");
}

// ---------------- launch ----------------------------------------------------------
extern "C" void kernel_launch(void* const* d_in, const int* in_sizes, int n_in,
                              void* d_out, int out_size) {
    const float* sess = (const float*)d_in[0];
    const float* ue   = (const float*)d_in[1];
    const int*   ids  = (const int*)d_in[2];   // JAX x64 disabled: int32
    const float* Wq   = (const float*)d_in[3];
    const float* Wk   = (const float*)d_in[4];
    const float* Wv   = (const float*)d_in[5];
    const float* W1   = (const float*)d_in[6];
    const float* b1   = (const float*)d_in[7];
    float*       out  = (float*)d_out;
    int N = in_sizes[0] / HH;   // 200000

    static bool attr_set = false;
    if (!attr_set) {
        cudaFuncSetAttribute(k_mma<0>, cudaFuncAttributeMaxDynamicSharedMemorySize, 2 * STAGE_BYTES);
        cudaFuncSetAttribute(k_mma<2>, cudaFuncAttributeMaxDynamicSharedMemorySize, 2 * STAGE_BYTES);
        attr_set = true;
    }

    int nblk = (N + BM - 1) / BM;
    k_zero<<<UU * HH / 256, 256>>>();
    k_prepT<<<dim3(8, 8, 2), 256>>>(Wq, Wk, Wv, W1);
    k_prepBt<<<256, 256>>>(W1);
    k_cvtA<<<N * (HH / 4) / 256, 256>>>((const float4*)ue);
    k_mma<0><<<nblk, 512, 2 * STAGE_BYTES>>>(sess, ids, nullptr, N);
    k_scatter<<<N / 4, 256>>>(ue, ids);
    k_gemmU<<<(UU + 63) / 64, 256>>>(b1);
    k_mma<2><<<nblk, 512, 2 * STAGE_BYTES>>>(nullptr, ids, out, N);
}

// round 6
// speedup vs baseline: 1.6451x; 1.0312x over previous
#include <cuda_runtime.h>
#include <cuda_bf16.h>
#include <cstdint>

#define NN 200000
#define UU 20000
#define HH 256

#define BM 128
#define BN 256
#define BK 32
#define KS 40                 // padded k-stride in bf16 elems (80 bytes)
#define STAGE_BYTES 61440
#define AH_OFF 0
#define AL_OFF 10240
#define BH_OFF 20480
#define BL_OFF 40960
#define NSTAGE 3

// ---------------- scratch (device globals) -------------------------------------
__device__ __align__(16) __nv_bfloat16 g_Ah[(size_t)NN * HH];
__device__ __align__(16) __nv_bfloat16 g_Al[(size_t)NN * HH];
__device__ __align__(16) __nv_bfloat16 g_Wh[(size_t)UU * HH];   // ws hi/lo
__device__ __align__(16) __nv_bfloat16 g_Wl[(size_t)UU * HH];
__device__ __align__(16) __nv_bfloat16 g_Mth [HH * HH], g_Mtl [HH * HH];  // M^T  hi/lo (n-major)
__device__ __align__(16) __nv_bfloat16 g_C1th[HH * HH], g_C1tl[HH * HH];  // C1^T hi/lo
__device__ __align__(16) __nv_bfloat16 g_Bth [HH * HH], g_Btl [HH * HH];  // W1[:,H:]  (n-major) hi/lo
__device__ __align__(16) float    g_ws [UU * HH];
__device__ __align__(16) float    g_D  [UU * HH];
__device__ __align__(16) float    g_sim[NN];
__device__ __align__(16) unsigned g_smax[UU];
__device__ __align__(16) float    g_denom[UU];

// ---------------- helpers -------------------------------------------------------
__device__ __forceinline__ unsigned fenc(float f) {
    unsigned u = __float_as_uint(f);
    return (u & 0x80000000u) ? ~u : (u | 0x80000000u);
}
__device__ __forceinline__ float fdec(unsigned u) {
    return (u & 0x80000000u) ? __uint_as_float(u & 0x7FFFFFFFu) : __uint_as_float(~u);
}
__device__ __forceinline__ void ldsm4(uint32_t* r, uint32_t addr) {
    asm volatile("ldmatrix.sync.aligned.m8n8.x4.shared.b16 {%0,%1,%2,%3}, [%4];"
                 : "=r"(r[0]), "=r"(r[1]), "=r"(r[2]), "=r"(r[3]) : "r"(addr));
}
__device__ __forceinline__ void mma16816(float* c, const uint32_t* a, const uint32_t* b) {
    asm volatile("mma.sync.aligned.m16n8k16.row.col.f32.bf16.bf16.f32 "
                 "{%0,%1,%2,%3}, {%4,%5,%6,%7}, {%8,%9}, {%0,%1,%2,%3};"
                 : "+f"(c[0]), "+f"(c[1]), "+f"(c[2]), "+f"(c[3])
                 : "r"(a[0]), "r"(a[1]), "r"(a[2]), "r"(a[3]), "r"(b[0]), "r"(b[1]));
}
__device__ __forceinline__ void cpa16(uint32_t dst, const void* src, bool v) {
    int sz = v ? 16 : 0;
    asm volatile("cp.async.cg.shared.global [%0], [%1], 16, %2;"
                 :: "r"(dst), "l"(src), "r"(sz));
}

// ---------------- init scratch -------------------------------------------------
__global__ void k_zero() {
    int idx = blockIdx.x * 256 + threadIdx.x;   // 20000 blocks -> UU*HH
    g_ws[idx] = 0.0f;
    if (idx < UU) { g_denom[idx] = 0.0f; g_smax[idx] = 0u; }
}

// ---------------- coalesced precompute GEMMs -----------------------------------
// z==0: M[a,t]  = Wq[a,:]·Wk[t,:]      -> g_Mth/l [t*256+a]
// z==1: C1[a,t] = Wv[a,:]·W1[t,0:256]  -> g_C1th/l[t*256+a]
__global__ void k_prepT(const float* __restrict__ Wq, const float* __restrict__ Wk,
                        const float* __restrict__ Wv, const float* __restrict__ W1) {
    __shared__ float As[32 * 129];
    __shared__ float Bs[32 * 129];
    int z = blockIdx.z;
    int tid = threadIdx.x;
    int abase = blockIdx.y * 32;
    int tbase = blockIdx.x * 32;
    const float* Ag = z ? Wv : Wq;
    int tx = tid & 31, ty = tid >> 5;
    float acc[4] = {0.f, 0.f, 0.f, 0.f};

    for (int kt = 0; kt < 256; kt += 128) {
        #pragma unroll
        for (int i = 0; i < 16; i++) {
            int f = tid + i * 256;
            int r = f >> 7, c = f & 127;
            As[r * 129 + c] = Ag[(abase + r) * 256 + kt + c];
            Bs[r * 129 + c] = z ? W1[(tbase + r) * 512 + kt + c]
                                : Wk[(tbase + r) * 256 + kt + c];
        }
        __syncthreads();
        #pragma unroll 4
        for (int k = 0; k < 128; k++) {
            float av = As[tx * 129 + k];
            #pragma unroll
            for (int j = 0; j < 4; j++) acc[j] += av * Bs[(ty + 8 * j) * 129 + k];
        }
        __syncthreads();
    }
    int a = abase + tx;
    #pragma unroll
    for (int j = 0; j < 4; j++) {
        int t = tbase + ty + 8 * j;
        __nv_bfloat16 h = __float2bfloat16(acc[j]);
        __nv_bfloat16 l = __float2bfloat16(acc[j] - __bfloat162float(h));
        if (z == 0) { g_Mth [t * 256 + a] = h; g_Mtl [t * 256 + a] = l; }
        else        { g_C1th[t * 256 + a] = h; g_C1tl[t * 256 + a] = l; }
    }
}

// Bt (n-major, bf16 hi/lo): g_Bth[j*256+k] = W1[j*512+256+k]
__global__ void k_prepBt(const float* __restrict__ W1) {
    int j = blockIdx.x, k = threadIdx.x;
    float v = W1[j * 512 + 256 + k];
    __nv_bfloat16 h = __float2bfloat16(v);
    g_Bth[j * 256 + k] = h;
    g_Btl[j * 256 + k] = __float2bfloat16(v - __bfloat162float(h));
}

// ---------------- fp32 -> bf16 hi/lo split ---------------------------------------
__global__ void k_cvt(const float4* __restrict__ src,
                      __nv_bfloat16* __restrict__ dH, __nv_bfloat16* __restrict__ dL) {
    size_t i = (size_t)blockIdx.x * 256 + threadIdx.x;
    float4 v = src[i];
    __nv_bfloat16 h0 = __float2bfloat16(v.x), h1 = __float2bfloat16(v.y);
    __nv_bfloat16 h2 = __float2bfloat16(v.z), h3 = __float2bfloat16(v.w);
    __nv_bfloat162* H2 = (__nv_bfloat162*)dH;
    H2[i * 2 + 0] = __halves2bfloat162(h0, h1);
    H2[i * 2 + 1] = __halves2bfloat162(h2, h3);
    __nv_bfloat16 l0 = __float2bfloat16(v.x - __bfloat162float(h0));
    __nv_bfloat16 l1 = __float2bfloat16(v.y - __bfloat162float(h1));
    __nv_bfloat16 l2 = __float2bfloat16(v.z - __bfloat162float(h2));
    __nv_bfloat16 l3 = __float2bfloat16(v.w - __bfloat162float(h3));
    __nv_bfloat162* L2 = (__nv_bfloat162*)dL;
    L2[i * 2 + 0] = __halves2bfloat162(l0, l1);
    L2[i * 2 + 1] = __halves2bfloat162(l2, l3);
}

// ---------------- tensor-core GEMM (split-bf16, 3 MMAs, 3-stage pipeline) -------
// MODE 0: sim = rowsum((A @ M) .* sess); g_sim; segment atomicMax   (A = ue)
// MODE 1: g_D = (ws @ Bt)/denom + b1                                 (A = ws, extra = b1)
// MODE 2: out = relu(A @ C1 + g_D[ids])                              (A = ue)
template<int MODE>
__global__ __launch_bounds__(512, 1)
void k_mma(const float* __restrict__ extra, const int* __restrict__ ids,
           float* __restrict__ outp, int nrows) {
    extern __shared__ __align__(16) char smem[];
    uint32_t sbase = (uint32_t)__cvta_generic_to_shared(smem);
    const int tid  = threadIdx.x;
    const int lane = tid & 31;
    const int wid  = tid >> 5;
    const int mw = wid >> 2, nw = wid & 3;
    const int blockRow = blockIdx.x * BM;

    const __nv_bfloat16* Ahp = (MODE == 1) ? g_Wh : g_Ah;
    const __nv_bfloat16* Alp = (MODE == 1) ? g_Wl : g_Al;
    const __nv_bfloat16* Bth = (MODE == 0) ? g_Mth : ((MODE == 1) ? g_Bth : g_C1th);
    const __nv_bfloat16* Btl = (MODE == 0) ? g_Mtl : ((MODE == 1) ? g_Btl : g_C1tl);

    float acc[2][8][4];
    #pragma unroll
    for (int t = 0; t < 2; t++)
        #pragma unroll
        for (int j = 0; j < 8; j++)
            #pragma unroll
            for (int c = 0; c < 4; c++) acc[t][j][c] = 0.0f;

    // ---- async tile loader (stage s, k-tile kt) ----
    auto load_stage = [&](int kt, int s) {
        uint32_t db = sbase + (uint32_t)s * STAGE_BYTES;
        {   // A hi/lo: 128 rows x 32 bf16 = 512 chunks of 16B each
            int r = tid >> 2, ch = tid & 3;
            int grow = blockRow + r;
            bool v = grow < nrows;
            size_t gi = (size_t)(v ? grow : 0) * HH + kt * BK + ch * 8;
            cpa16(db + AH_OFF + r * 80 + ch * 16, Ahp + gi, v);
            cpa16(db + AL_OFF + r * 80 + ch * 16, Alp + gi, v);
        }
        #pragma unroll
        for (int i = 0; i < 2; i++) {   // B hi/lo: 256 rows x 32 bf16
            int c = tid * 2 + i;
            int r = c >> 2, ch = c & 3;
            size_t gi = (size_t)r * HH + kt * BK + ch * 8;
            cpa16(db + BH_OFF + r * 80 + ch * 16, Bth + gi, true);
            cpa16(db + BL_OFF + r * 80 + ch * 16, Btl + gi, true);
        }
        asm volatile("cp.async.commit_group;" ::: "memory");
    };

    load_stage(0, 0);
    load_stage(1, 1);

    const int NKT = HH / BK;   // 8
    for (int kt = 0; kt < NKT; kt++) {
        if (kt < NKT - 1) asm volatile("cp.async.wait_group 1;" ::: "memory");
        else              asm volatile("cp.async.wait_group 0;" ::: "memory");
        __syncthreads();
        if (kt + 2 < NKT) load_stage(kt + 2, (kt + 2) % NSTAGE);

        uint32_t sb = sbase + (uint32_t)(kt % NSTAGE) * STAGE_BYTES;
        #pragma unroll
        for (int k16 = 0; k16 < BK; k16 += 16) {
            uint32_t ah[2][4], al[2][4];
            #pragma unroll
            for (int t = 0; t < 2; t++) {
                uint32_t ao = (uint32_t)(((mw * 32 + t * 16 + (lane & 15)) * KS
                                          + k16 + ((lane >> 4) << 3)) * 2);
                ldsm4(ah[t], sb + AH_OFF + ao);
                ldsm4(al[t], sb + AL_OFF + ao);
            }
            #pragma unroll
            for (int p = 0; p < 4; p++) {
                uint32_t bo = (uint32_t)(((nw * 64 + p * 16 + (lane & 7) + ((lane >> 4) << 3)) * KS
                                          + k16 + (lane & 8)) * 2);
                uint32_t bh[4], bl[4];
                ldsm4(bh, sb + BH_OFF + bo);
                ldsm4(bl, sb + BL_OFF + bo);
                // three sweeps over the 4 independent accumulators (reuse distance 4)
                #pragma unroll
                for (int t = 0; t < 2; t++)
                    #pragma unroll
                    for (int q = 0; q < 2; q++)
                        mma16816(acc[t][p * 2 + q], ah[t], &bh[2 * q]);
                #pragma unroll
                for (int t = 0; t < 2; t++)
                    #pragma unroll
                    for (int q = 0; q < 2; q++)
                        mma16816(acc[t][p * 2 + q], ah[t], &bl[2 * q]);
                #pragma unroll
                for (int t = 0; t < 2; t++)
                    #pragma unroll
                    for (int q = 0; q < 2; q++)
                        mma16816(acc[t][p * 2 + q], al[t], &bh[2 * q]);
            }
        }
        // no trailing barrier: next iteration's wait+sync protects stage reuse
    }

    const int lr = lane >> 2;           // 0..7
    const int lc = (lane & 3) * 2;      // 0,2,4,6

    if (MODE == 0) {
        float part[2][2] = {{0.f, 0.f}, {0.f, 0.f}};
        #pragma unroll
        for (int t = 0; t < 2; t++) {
            int row0 = blockRow + mw * 32 + t * 16 + lr;
            #pragma unroll
            for (int j = 0; j < 8; j++) {
                int col = nw * 64 + j * 8 + lc;
                if (row0 < nrows) {
                    float2 s = *(const float2*)&extra[(size_t)row0 * 256 + col];
                    part[t][0] += acc[t][j][0] * s.x + acc[t][j][1] * s.y;
                }
                if (row0 + 8 < nrows) {
                    float2 s = *(const float2*)&extra[(size_t)(row0 + 8) * 256 + col];
                    part[t][1] += acc[t][j][2] * s.x + acc[t][j][3] * s.y;
                }
            }
        }
        #pragma unroll
        for (int t = 0; t < 2; t++)
            #pragma unroll
            for (int h = 0; h < 2; h++) {
                part[t][h] += __shfl_xor_sync(0xffffffffu, part[t][h], 1);
                part[t][h] += __shfl_xor_sync(0xffffffffu, part[t][h], 2);
            }
        __syncthreads();                 // all stage reads done before smem reuse
        float* red = (float*)smem;       // [128][4]
        if ((lane & 3) == 0) {
            #pragma unroll
            for (int t = 0; t < 2; t++) {
                red[(mw * 32 + t * 16 + lr) * 4 + nw]     = part[t][0];
                red[(mw * 32 + t * 16 + lr + 8) * 4 + nw] = part[t][1];
            }
        }
        __syncthreads();
        if (tid < 128) {
            int row = blockRow + tid;
            if (row < nrows) {
                float s = red[tid * 4] + red[tid * 4 + 1] + red[tid * 4 + 2] + red[tid * 4 + 3];
                g_sim[row] = s;
                atomicMax(&g_smax[ids[row]], fenc(s));
            }
        }
    } else if (MODE == 1) {
        #pragma unroll
        for (int t = 0; t < 2; t++)
            #pragma unroll
            for (int h = 0; h < 2; h++) {
                int row = blockRow + mw * 32 + t * 16 + lr + h * 8;
                if (row >= nrows) continue;
                float inv = 1.0f / g_denom[row];
                #pragma unroll
                for (int j = 0; j < 8; j++) {
                    int col = nw * 64 + j * 8 + lc;
                    float2 b = *(const float2*)&extra[col];
                    float2 o;
                    o.x = acc[t][j][2 * h + 0] * inv + b.x;
                    o.y = acc[t][j][2 * h + 1] * inv + b.y;
                    *(float2*)&g_D[(size_t)row * 256 + col] = o;
                }
            }
    } else {
        #pragma unroll
        for (int t = 0; t < 2; t++)
            #pragma unroll
            for (int h = 0; h < 2; h++) {
                int row = blockRow + mw * 32 + t * 16 + lr + h * 8;
                if (row >= nrows) continue;
                int uid = ids[row];
                const float* Dr = g_D + (size_t)uid * 256;
                #pragma unroll
                for (int j = 0; j < 8; j++) {
                    int col = nw * 64 + j * 8 + lc;
                    float2 d = *(const float2*)&Dr[col];
                    float2 o;
                    o.x = fmaxf(acc[t][j][2 * h + 0] + d.x, 0.0f);
                    o.y = fmaxf(acc[t][j][2 * h + 1] + d.y, 0.0f);
                    *(float2*)&outp[(size_t)row * 256 + col] = o;
                }
            }
    }
}

// ---------------- exp + scatter --------------------------------------------------
__global__ void k_scatter(const float* __restrict__ ue, const int* __restrict__ ids) {
    int i    = blockIdx.x * 4 + (threadIdx.x >> 6);
    int lane = threadIdx.x & 63;
    int uid  = ids[i];
    float mx = fdec(g_smax[uid]);
    float e  = expf(g_sim[i] - mx);
    if (lane == 0) atomicAdd(&g_denom[uid], e);
    float4 u4 = *(const float4*)&ue[(size_t)i * 256 + lane * 4];
    float* p = &g_ws[(size_t)uid * 256 + lane * 4];
    asm volatile("red.global.add.v4.f32 [%0], {%1, %2, %3, %4};"
                 :: "l"(p), "f"(u4.x * e), "f"(u4.y * e), "f"(u4.z * e), "f"(u4.w * e)
                 : "memory");
}

// ---------------- launch ----------------------------------------------------------
extern "C" void kernel_launch(void* const* d_in, const int* in_sizes, int n_in,
                              void* d_out, int out_size) {
    const float* sess = (const float*)d_in[0];
    const float* ue   = (const float*)d_in[1];
    const int*   ids  = (const int*)d_in[2];   // JAX x64 disabled: int32
    const float* Wq   = (const float*)d_in[3];
    const float* Wk   = (const float*)d_in[4];
    const float* Wv   = (const float*)d_in[5];
    const float* W1   = (const float*)d_in[6];
    const float* b1   = (const float*)d_in[7];
    float*       out  = (float*)d_out;
    int N = in_sizes[0] / HH;   // 200000

    static bool attr_set = false;
    if (!attr_set) {
        cudaFuncSetAttribute(k_mma<0>, cudaFuncAttributeMaxDynamicSharedMemorySize, NSTAGE * STAGE_BYTES);
        cudaFuncSetAttribute(k_mma<1>, cudaFuncAttributeMaxDynamicSharedMemorySize, NSTAGE * STAGE_BYTES);
        cudaFuncSetAttribute(k_mma<2>, cudaFuncAttributeMaxDynamicSharedMemorySize, NSTAGE * STAGE_BYTES);
        attr_set = true;
    }

    float* d_ws;
    cudaGetSymbolAddress((void**)&d_ws, g_ws);
    __nv_bfloat16 *d_Wh, *d_Wl, *d_Ah, *d_Al;
    cudaGetSymbolAddress((void**)&d_Wh, g_Wh);
    cudaGetSymbolAddress((void**)&d_Wl, g_Wl);
    cudaGetSymbolAddress((void**)&d_Ah, g_Ah);
    cudaGetSymbolAddress((void**)&d_Al, g_Al);

    int nblk = (N + BM - 1) / BM;
    k_zero<<<UU * HH / 256, 256>>>();
    k_prepT<<<dim3(8, 8, 2), 256>>>(Wq, Wk, Wv, W1);
    k_prepBt<<<256, 256>>>(W1);
    k_cvt<<<N * (HH / 4) / 256, 256>>>((const float4*)ue, d_Ah, d_Al);
    k_mma<0><<<nblk, 512, NSTAGE * STAGE_BYTES>>>(sess, ids, nullptr, N);
    k_scatter<<<N / 4, 256>>>(ue, ids);
    k_cvt<<<UU * (HH / 4) / 256, 256>>>((const float4*)d_ws, d_Wh, d_Wl);
    k_mma<1><<<(UU + BM - 1) / BM, 512, NSTAGE * STAGE_BYTES>>>(b1, nullptr, nullptr, UU);
    k_mma<2><<<nblk, 512, NSTAGE * STAGE_BYTES>>>(nullptr, ids, out, N);
}

// round 7
// speedup vs baseline: 1.9318x; 1.1743x over previous
#include <cuda_runtime.h>
#include <cuda_bf16.h>
#include <cstdint>

#define NN 200000
#define UU 20000
#define HH 256

#define BM 128
#define BN 128
#define BK 32
#define KS 40                 // padded k-stride in bf16 elems (80 bytes)
#define STAGE_BYTES 40960
#define AH_OFF 0
#define AL_OFF 10240
#define BH_OFF 20480
#define BL_OFF 30720
#define NSTAGE 2

// ---------------- scratch (device globals) -------------------------------------
__device__ __align__(16) __nv_bfloat16 g_Ah[(size_t)NN * HH];
__device__ __align__(16) __nv_bfloat16 g_Al[(size_t)NN * HH];
__device__ __align__(16) __nv_bfloat16 g_Wh[(size_t)UU * HH];   // ws hi/lo
__device__ __align__(16) __nv_bfloat16 g_Wl[(size_t)UU * HH];
__device__ __align__(16) __nv_bfloat16 g_Mth [HH * HH], g_Mtl [HH * HH];  // M^T  hi/lo (n-major)
__device__ __align__(16) __nv_bfloat16 g_C1th[HH * HH], g_C1tl[HH * HH];  // C1^T hi/lo
__device__ __align__(16) __nv_bfloat16 g_Bth [HH * HH], g_Btl [HH * HH];  // W1[:,H:]  (n-major) hi/lo
__device__ __align__(16) float    g_ws [UU * HH];
__device__ __align__(16) float    g_D  [UU * HH];
__device__ __align__(16) float    g_sim[NN];
__device__ __align__(16) unsigned g_smax[UU];
__device__ __align__(16) float    g_denom[UU];

// ---------------- helpers -------------------------------------------------------
__device__ __forceinline__ unsigned fenc(float f) {
    unsigned u = __float_as_uint(f);
    return (u & 0x80000000u) ? ~u : (u | 0x80000000u);
}
__device__ __forceinline__ float fdec(unsigned u) {
    return (u & 0x80000000u) ? __uint_as_float(u & 0x7FFFFFFFu) : __uint_as_float(~u);
}
__device__ __forceinline__ void ldsm4(uint32_t* r, uint32_t addr) {
    asm volatile("ldmatrix.sync.aligned.m8n8.x4.shared.b16 {%0,%1,%2,%3}, [%4];"
                 : "=r"(r[0]), "=r"(r[1]), "=r"(r[2]), "=r"(r[3]) : "r"(addr));
}
__device__ __forceinline__ void mma16816(float* c, const uint32_t* a, const uint32_t* b) {
    asm volatile("mma.sync.aligned.m16n8k16.row.col.f32.bf16.bf16.f32 "
                 "{%0,%1,%2,%3}, {%4,%5,%6,%7}, {%8,%9}, {%0,%1,%2,%3};"
                 : "+f"(c[0]), "+f"(c[1]), "+f"(c[2]), "+f"(c[3])
                 : "r"(a[0]), "r"(a[1]), "r"(a[2]), "r"(a[3]), "r"(b[0]), "r"(b[1]));
}
__device__ __forceinline__ void cpa16(uint32_t dst, const void* src, bool v) {
    int sz = v ? 16 : 0;
    asm volatile("cp.async.cg.shared.global [%0], [%1], 16, %2;"
                 :: "r"(dst), "l"(src), "r"(sz));
}

// ---------------- init scratch -------------------------------------------------
__global__ void k_zero() {
    int idx = blockIdx.x * 256 + threadIdx.x;   // 20000 blocks -> UU*HH threads
    g_ws[idx] = 0.0f;
    if (idx < NN) g_sim[idx] = 0.0f;
    if (idx < UU) { g_denom[idx] = 0.0f; g_smax[idx] = 0u; }
}

// ---------------- coalesced precompute GEMMs -----------------------------------
// z==0: M[a,t]  = Wq[a,:]·Wk[t,:]      -> g_Mth/l [t*256+a]
// z==1: C1[a,t] = Wv[a,:]·W1[t,0:256]  -> g_C1th/l[t*256+a]
__global__ void k_prepT(const float* __restrict__ Wq, const float* __restrict__ Wk,
                        const float* __restrict__ Wv, const float* __restrict__ W1) {
    __shared__ float As[32 * 129];
    __shared__ float Bs[32 * 129];
    int z = blockIdx.z;
    int tid = threadIdx.x;
    int abase = blockIdx.y * 32;
    int tbase = blockIdx.x * 32;
    const float* Ag = z ? Wv : Wq;
    int tx = tid & 31, ty = tid >> 5;
    float acc[4] = {0.f, 0.f, 0.f, 0.f};

    for (int kt = 0; kt < 256; kt += 128) {
        #pragma unroll
        for (int i = 0; i < 16; i++) {
            int f = tid + i * 256;
            int r = f >> 7, c = f & 127;
            As[r * 129 + c] = Ag[(abase + r) * 256 + kt + c];
            Bs[r * 129 + c] = z ? W1[(tbase + r) * 512 + kt + c]
                                : Wk[(tbase + r) * 256 + kt + c];
        }
        __syncthreads();
        #pragma unroll 4
        for (int k = 0; k < 128; k++) {
            float av = As[tx * 129 + k];
            #pragma unroll
            for (int j = 0; j < 4; j++) acc[j] += av * Bs[(ty + 8 * j) * 129 + k];
        }
        __syncthreads();
    }
    int a = abase + tx;
    #pragma unroll
    for (int j = 0; j < 4; j++) {
        int t = tbase + ty + 8 * j;
        __nv_bfloat16 h = __float2bfloat16(acc[j]);
        __nv_bfloat16 l = __float2bfloat16(acc[j] - __bfloat162float(h));
        if (z == 0) { g_Mth [t * 256 + a] = h; g_Mtl [t * 256 + a] = l; }
        else        { g_C1th[t * 256 + a] = h; g_C1tl[t * 256 + a] = l; }
    }
}

// Bt (n-major, bf16 hi/lo): g_Bth[j*256+k] = W1[j*512+256+k]
__global__ void k_prepBt(const float* __restrict__ W1) {
    int j = blockIdx.x, k = threadIdx.x;
    float v = W1[j * 512 + 256 + k];
    __nv_bfloat16 h = __float2bfloat16(v);
    g_Bth[j * 256 + k] = h;
    g_Btl[j * 256 + k] = __float2bfloat16(v - __bfloat162float(h));
}

// ---------------- fp32 -> bf16 hi/lo split ---------------------------------------
__global__ void k_cvt(const float4* __restrict__ src,
                      __nv_bfloat16* __restrict__ dH, __nv_bfloat16* __restrict__ dL) {
    size_t i = (size_t)blockIdx.x * 256 + threadIdx.x;
    float4 v = src[i];
    __nv_bfloat16 h0 = __float2bfloat16(v.x), h1 = __float2bfloat16(v.y);
    __nv_bfloat16 h2 = __float2bfloat16(v.z), h3 = __float2bfloat16(v.w);
    __nv_bfloat162* H2 = (__nv_bfloat162*)dH;
    H2[i * 2 + 0] = __halves2bfloat162(h0, h1);
    H2[i * 2 + 1] = __halves2bfloat162(h2, h3);
    __nv_bfloat16 l0 = __float2bfloat16(v.x - __bfloat162float(h0));
    __nv_bfloat16 l1 = __float2bfloat16(v.y - __bfloat162float(h1));
    __nv_bfloat16 l2 = __float2bfloat16(v.z - __bfloat162float(h2));
    __nv_bfloat16 l3 = __float2bfloat16(v.w - __bfloat162float(h3));
    __nv_bfloat162* L2 = (__nv_bfloat162*)dL;
    L2[i * 2 + 0] = __halves2bfloat162(l0, l1);
    L2[i * 2 + 1] = __halves2bfloat162(l2, l3);
}

// ---------------- tensor-core GEMM (split-bf16, BM=128 BN=128, 2 CTA/SM) --------
// grid = (rowBlocks, 2): blockIdx.y selects 128-col half
// MODE 0: g_sim[row] += partial rowsum((A @ M) .* sess)               (A = ue)
// MODE 1: g_D = (ws @ Bt)/denom + b1                                   (A = ws, extra = b1)
// MODE 2: out = relu(A @ C1 + g_D[ids])                                (A = ue)
template<int MODE>
__global__ __launch_bounds__(256, 2)
void k_mma(const float* __restrict__ extra, const int* __restrict__ ids,
           float* __restrict__ outp, int nrows) {
    extern __shared__ __align__(16) char smem[];
    uint32_t sbase = (uint32_t)__cvta_generic_to_shared(smem);
    const int tid  = threadIdx.x;
    const int lane = tid & 31;
    const int wid  = tid >> 5;
    const int mw = wid >> 1, nw = wid & 1;     // 4 x 2 warp grid
    const int blockRow = blockIdx.x * BM;
    const int colBase  = blockIdx.y * BN;

    const __nv_bfloat16* Ahp = (MODE == 1) ? g_Wh : g_Ah;
    const __nv_bfloat16* Alp = (MODE == 1) ? g_Wl : g_Al;
    const __nv_bfloat16* Bth = (MODE == 0) ? g_Mth : ((MODE == 1) ? g_Bth : g_C1th);
    const __nv_bfloat16* Btl = (MODE == 0) ? g_Mtl : ((MODE == 1) ? g_Btl : g_C1tl);

    float acc[2][8][4];
    #pragma unroll
    for (int t = 0; t < 2; t++)
        #pragma unroll
        for (int j = 0; j < 8; j++)
            #pragma unroll
            for (int c = 0; c < 4; c++) acc[t][j][c] = 0.0f;

    // ---- async tile loader (stage s, k-tile kt): 8 cpa16 per thread ----
    auto load_stage = [&](int kt, int s) {
        uint32_t db = sbase + (uint32_t)s * STAGE_BYTES;
        #pragma unroll
        for (int l = 0; l < 2; l++) {
            int u = tid + l * 256;
            int r = u >> 2, ch = u & 3;
            // A hi/lo
            int grow = blockRow + r;
            bool v = grow < nrows;
            size_t ga = (size_t)(v ? grow : 0) * HH + kt * BK + ch * 8;
            cpa16(db + AH_OFF + r * 80 + ch * 16, Ahp + ga, v);
            cpa16(db + AL_OFF + r * 80 + ch * 16, Alp + ga, v);
            // B hi/lo (n-rows colBase..colBase+127)
            size_t gb = (size_t)(colBase + r) * HH + kt * BK + ch * 8;
            cpa16(db + BH_OFF + r * 80 + ch * 16, Bth + gb, true);
            cpa16(db + BL_OFF + r * 80 + ch * 16, Btl + gb, true);
        }
        asm volatile("cp.async.commit_group;" ::: "memory");
    };

    load_stage(0, 0);
    load_stage(1, 1);

    const int NKT = HH / BK;   // 8
    for (int kt = 0; kt < NKT; kt++) {
        if (kt < NKT - 1) asm volatile("cp.async.wait_group 1;" ::: "memory");
        else              asm volatile("cp.async.wait_group 0;" ::: "memory");
        __syncthreads();

        uint32_t sb = sbase + (uint32_t)(kt & 1) * STAGE_BYTES;
        #pragma unroll
        for (int k16 = 0; k16 < BK; k16 += 16) {
            uint32_t ah[2][4], al[2][4];
            #pragma unroll
            for (int t = 0; t < 2; t++) {
                uint32_t ao = (uint32_t)(((mw * 32 + t * 16 + (lane & 15)) * KS
                                          + k16 + ((lane >> 4) << 3)) * 2);
                ldsm4(ah[t], sb + AH_OFF + ao);
                ldsm4(al[t], sb + AL_OFF + ao);
            }
            #pragma unroll
            for (int p = 0; p < 4; p++) {
                uint32_t bo = (uint32_t)(((nw * 64 + p * 16 + (lane & 7) + ((lane >> 4) << 3)) * KS
                                          + k16 + (lane & 8)) * 2);
                uint32_t bh[4], bl[4];
                ldsm4(bh, sb + BH_OFF + bo);
                ldsm4(bl, sb + BL_OFF + bo);
                #pragma unroll
                for (int t = 0; t < 2; t++)
                    #pragma unroll
                    for (int q = 0; q < 2; q++)
                        mma16816(acc[t][p * 2 + q], ah[t], &bh[2 * q]);
                #pragma unroll
                for (int t = 0; t < 2; t++)
                    #pragma unroll
                    for (int q = 0; q < 2; q++)
                        mma16816(acc[t][p * 2 + q], ah[t], &bl[2 * q]);
                #pragma unroll
                for (int t = 0; t < 2; t++)
                    #pragma unroll
                    for (int q = 0; q < 2; q++)
                        mma16816(acc[t][p * 2 + q], al[t], &bh[2 * q]);
            }
        }
        __syncthreads();                                    // stage fully consumed
        if (kt + 2 < NKT) load_stage(kt + 2, kt & 1);       // refill same stage
    }

    const int lr = lane >> 2;           // 0..7
    const int lc = (lane & 3) * 2;      // 0,2,4,6

    if (MODE == 0) {
        float part[2][2] = {{0.f, 0.f}, {0.f, 0.f}};
        #pragma unroll
        for (int t = 0; t < 2; t++) {
            int row0 = blockRow + mw * 32 + t * 16 + lr;
            #pragma unroll
            for (int j = 0; j < 8; j++) {
                int col = colBase + nw * 64 + j * 8 + lc;
                if (row0 < nrows) {
                    float2 s = *(const float2*)&extra[(size_t)row0 * 256 + col];
                    part[t][0] += acc[t][j][0] * s.x + acc[t][j][1] * s.y;
                }
                if (row0 + 8 < nrows) {
                    float2 s = *(const float2*)&extra[(size_t)(row0 + 8) * 256 + col];
                    part[t][1] += acc[t][j][2] * s.x + acc[t][j][3] * s.y;
                }
            }
        }
        #pragma unroll
        for (int t = 0; t < 2; t++)
            #pragma unroll
            for (int h = 0; h < 2; h++) {
                part[t][h] += __shfl_xor_sync(0xffffffffu, part[t][h], 1);
                part[t][h] += __shfl_xor_sync(0xffffffffu, part[t][h], 2);
            }
        __syncthreads();                 // stage reads done before smem reuse
        float* red = (float*)smem;       // [128][2]
        if ((lane & 3) == 0) {
            #pragma unroll
            for (int t = 0; t < 2; t++) {
                red[(mw * 32 + t * 16 + lr) * 2 + nw]     = part[t][0];
                red[(mw * 32 + t * 16 + lr + 8) * 2 + nw] = part[t][1];
            }
        }
        __syncthreads();
        if (tid < 128) {
            int row = blockRow + tid;
            if (row < nrows) {
                float s = red[tid * 2] + red[tid * 2 + 1];
                asm volatile("red.global.add.f32 [%0], %1;"
                             :: "l"(g_sim + row), "f"(s) : "memory");
            }
        }
    } else if (MODE == 1) {
        #pragma unroll
        for (int t = 0; t < 2; t++)
            #pragma unroll
            for (int h = 0; h < 2; h++) {
                int row = blockRow + mw * 32 + t * 16 + lr + h * 8;
                if (row >= nrows) continue;
                float inv = 1.0f / g_denom[row];
                #pragma unroll
                for (int j = 0; j < 8; j++) {
                    int col = colBase + nw * 64 + j * 8 + lc;
                    float2 b = *(const float2*)&extra[col];
                    float2 o;
                    o.x = acc[t][j][2 * h + 0] * inv + b.x;
                    o.y = acc[t][j][2 * h + 1] * inv + b.y;
                    *(float2*)&g_D[(size_t)row * 256 + col] = o;
                }
            }
    } else {
        #pragma unroll
        for (int t = 0; t < 2; t++)
            #pragma unroll
            for (int h = 0; h < 2; h++) {
                int row = blockRow + mw * 32 + t * 16 + lr + h * 8;
                if (row >= nrows) continue;
                int uid = ids[row];
                const float* Dr = g_D + (size_t)uid * 256;
                #pragma unroll
                for (int j = 0; j < 8; j++) {
                    int col = colBase + nw * 64 + j * 8 + lc;
                    float2 d = *(const float2*)&Dr[col];
                    float2 o;
                    o.x = fmaxf(acc[t][j][2 * h + 0] + d.x, 0.0f);
                    o.y = fmaxf(acc[t][j][2 * h + 1] + d.y, 0.0f);
                    *(float2*)&outp[(size_t)row * 256 + col] = o;
                }
            }
    }
}

// ---------------- segment max over completed sims --------------------------------
__global__ void k_smax(const int* __restrict__ ids, int n) {
    int i = blockIdx.x * 256 + threadIdx.x;
    if (i < n) atomicMax(&g_smax[ids[i]], fenc(g_sim[i]));
}

// ---------------- exp + scatter --------------------------------------------------
__global__ void k_scatter(const float* __restrict__ ue, const int* __restrict__ ids) {
    int i    = blockIdx.x * 4 + (threadIdx.x >> 6);
    int lane = threadIdx.x & 63;
    int uid  = ids[i];
    float mx = fdec(g_smax[uid]);
    float e  = expf(g_sim[i] - mx);
    if (lane == 0) atomicAdd(&g_denom[uid], e);
    float4 u4 = *(const float4*)&ue[(size_t)i * 256 + lane * 4];
    float* p = &g_ws[(size_t)uid * 256 + lane * 4];
    asm volatile("red.global.add.v4.f32 [%0], {%1, %2, %3, %4};"
                 :: "l"(p), "f"(u4.x * e), "f"(u4.y * e), "f"(u4.z * e), "f"(u4.w * e)
                 : "memory");
}

// ---------------- launch ----------------------------------------------------------
extern "C" void kernel_launch(void* const* d_in, const int* in_sizes, int n_in,
                              void* d_out, int out_size) {
    const float* sess = (const float*)d_in[0];
    const float* ue   = (const float*)d_in[1];
    const int*   ids  = (const int*)d_in[2];   // JAX x64 disabled: int32
    const float* Wq   = (const float*)d_in[3];
    const float* Wk   = (const float*)d_in[4];
    const float* Wv   = (const float*)d_in[5];
    const float* W1   = (const float*)d_in[6];
    const float* b1   = (const float*)d_in[7];
    float*       out  = (float*)d_out;
    int N = in_sizes[0] / HH;   // 200000

    static bool attr_set = false;
    if (!attr_set) {
        cudaFuncSetAttribute(k_mma<0>, cudaFuncAttributeMaxDynamicSharedMemorySize, NSTAGE * STAGE_BYTES);
        cudaFuncSetAttribute(k_mma<1>, cudaFuncAttributeMaxDynamicSharedMemorySize, NSTAGE * STAGE_BYTES);
        cudaFuncSetAttribute(k_mma<2>, cudaFuncAttributeMaxDynamicSharedMemorySize, NSTAGE * STAGE_BYTES);
        attr_set = true;
    }

    float* d_ws;
    cudaGetSymbolAddress((void**)&d_ws, g_ws);
    __nv_bfloat16 *d_Wh, *d_Wl, *d_Ah, *d_Al;
    cudaGetSymbolAddress((void**)&d_Wh, g_Wh);
    cudaGetSymbolAddress((void**)&d_Wl, g_Wl);
    cudaGetSymbolAddress((void**)&d_Ah, g_Ah);
    cudaGetSymbolAddress((void**)&d_Al, g_Al);

    dim3 gBig((N + BM - 1) / BM, 2);
    dim3 gU((UU + BM - 1) / BM, 2);
    k_zero<<<UU * HH / 256, 256>>>();
    k_prepT<<<dim3(8, 8, 2), 256>>>(Wq, Wk, Wv, W1);
    k_prepBt<<<256, 256>>>(W1);
    k_cvt<<<N * (HH / 4) / 256, 256>>>((const float4*)ue, d_Ah, d_Al);
    k_mma<0><<<gBig, 256, NSTAGE * STAGE_BYTES>>>(sess, ids, nullptr, N);
    k_smax<<<(N + 255) / 256, 256>>>(ids, N);
    k_scatter<<<N / 4, 256>>>(ue, ids);
    k_cvt<<<UU * (HH / 4) / 256, 256>>>((const float4*)d_ws, d_Wh, d_Wl);
    k_mma<1><<<gU, 256, NSTAGE * STAGE_BYTES>>>(b1, nullptr, nullptr, UU);
    k_mma<2><<<gBig, 256, NSTAGE * STAGE_BYTES>>>(nullptr, ids, out, N);
}

// round 8
// speedup vs baseline: 1.9544x; 1.0117x over previous
#include <cuda_runtime.h>
#include <cuda_bf16.h>
#include <cstdint>

#define NN 200000
#define UU 20000
#define HH 256

#define BM 128
#define BN 128
#define BK 32
#define KS 40                 // padded k-stride in bf16 elems (80 bytes)
#define STAGE_BYTES 40960
#define AH_OFF 0
#define AL_OFF 10240
#define BH_OFF 20480
#define BL_OFF 30720
#define NSTAGE 2

// ---------------- scratch (device globals) -------------------------------------
__device__ __align__(16) __nv_bfloat16 g_Ah[(size_t)NN * HH];
__device__ __align__(16) __nv_bfloat16 g_Al[(size_t)NN * HH];
__device__ __align__(16) __nv_bfloat16 g_Wh[(size_t)UU * HH];   // normalized ws hi/lo
__device__ __align__(16) __nv_bfloat16 g_Wl[(size_t)UU * HH];
__device__ __align__(16) __nv_bfloat16 g_Mth [HH * HH], g_Mtl [HH * HH];  // M^T  hi/lo (n-major)
__device__ __align__(16) __nv_bfloat16 g_C1th[HH * HH], g_C1tl[HH * HH];  // C1^T hi/lo
__device__ __align__(16) __nv_bfloat16 g_Bth [HH * HH], g_Btl [HH * HH];  // W1[:,H:]  (n-major) hi/lo
__device__ __align__(16) float    g_D  [UU * HH];
__device__ __align__(16) float    g_sim[NN];
__device__ int g_list[NN];          // CSR row lists
__device__ int g_off [UU + 1];
__device__ int g_cnt [UU];
__device__ int g_cnt2[UU];

// ---------------- helpers -------------------------------------------------------
__device__ __forceinline__ void ldsm4(uint32_t* r, uint32_t addr) {
    asm volatile("ldmatrix.sync.aligned.m8n8.x4.shared.b16 {%0,%1,%2,%3}, [%4];"
                 : "=r"(r[0]), "=r"(r[1]), "=r"(r[2]), "=r"(r[3]) : "r"(addr));
}
__device__ __forceinline__ void mma16816(float* c, const uint32_t* a, const uint32_t* b) {
    asm volatile("mma.sync.aligned.m16n8k16.row.col.f32.bf16.bf16.f32 "
                 "{%0,%1,%2,%3}, {%4,%5,%6,%7}, {%8,%9}, {%0,%1,%2,%3};"
                 : "+f"(c[0]), "+f"(c[1]), "+f"(c[2]), "+f"(c[3])
                 : "r"(a[0]), "r"(a[1]), "r"(a[2]), "r"(a[3]), "r"(b[0]), "r"(b[1]));
}
__device__ __forceinline__ void cpa16(uint32_t dst, const void* src, bool v) {
    int sz = v ? 16 : 0;
    asm volatile("cp.async.cg.shared.global [%0], [%1], 16, %2;"
                 :: "r"(dst), "l"(src), "r"(sz));
}

// ---------------- init scratch -------------------------------------------------
__global__ void k_zero() {
    int idx = blockIdx.x * 256 + threadIdx.x;   // 782 blocks
    if (idx < NN) g_sim[idx] = 0.0f;
    if (idx < UU) { g_cnt[idx] = 0; g_cnt2[idx] = 0; }
}

// ---------------- CSR build: hist -> scan -> fill --------------------------------
__global__ void k_hist(const int* __restrict__ ids, int n) {
    int i = blockIdx.x * 256 + threadIdx.x;
    if (i < n) atomicAdd(&g_cnt[ids[i]], 1);
}
__global__ void k_scan() {             // single block, 256 threads
    __shared__ int ps[256];
    const int C = (UU + 255) / 256;    // 79
    int t = threadIdx.x;
    int s = 0;
    for (int j = 0; j < C; j++) { int i = t * C + j; if (i < UU) s += g_cnt[i]; }
    ps[t] = s;
    __syncthreads();
    int acc = 0;
    for (int j = 0; j < t; j++) acc += ps[j];
    int run = acc;
    for (int j = 0; j < C; j++) {
        int i = t * C + j;
        if (i < UU) { g_off[i] = run; run += g_cnt[i]; }
    }
    if (t == 255) g_off[UU] = run;
}
__global__ void k_fill(const int* __restrict__ ids, int n) {
    int i = blockIdx.x * 256 + threadIdx.x;
    if (i < n) {
        int uid = ids[i];
        int pos = g_off[uid] + atomicAdd(&g_cnt2[uid], 1);
        g_list[pos] = i;
    }
}

// ---------------- coalesced precompute GEMMs -----------------------------------
// z==0: M[a,t]  = Wq[a,:]·Wk[t,:]      -> g_Mth/l [t*256+a]
// z==1: C1[a,t] = Wv[a,:]·W1[t,0:256]  -> g_C1th/l[t*256+a]
__global__ void k_prepT(const float* __restrict__ Wq, const float* __restrict__ Wk,
                        const float* __restrict__ Wv, const float* __restrict__ W1) {
    __shared__ float As[32 * 129];
    __shared__ float Bs[32 * 129];
    int z = blockIdx.z;
    int tid = threadIdx.x;
    int abase = blockIdx.y * 32;
    int tbase = blockIdx.x * 32;
    const float* Ag = z ? Wv : Wq;
    int tx = tid & 31, ty = tid >> 5;
    float acc[4] = {0.f, 0.f, 0.f, 0.f};

    for (int kt = 0; kt < 256; kt += 128) {
        #pragma unroll
        for (int i = 0; i < 16; i++) {
            int f = tid + i * 256;
            int r = f >> 7, c = f & 127;
            As[r * 129 + c] = Ag[(abase + r) * 256 + kt + c];
            Bs[r * 129 + c] = z ? W1[(tbase + r) * 512 + kt + c]
                                : Wk[(tbase + r) * 256 + kt + c];
        }
        __syncthreads();
        #pragma unroll 4
        for (int k = 0; k < 128; k++) {
            float av = As[tx * 129 + k];
            #pragma unroll
            for (int j = 0; j < 4; j++) acc[j] += av * Bs[(ty + 8 * j) * 129 + k];
        }
        __syncthreads();
    }
    int a = abase + tx;
    #pragma unroll
    for (int j = 0; j < 4; j++) {
        int t = tbase + ty + 8 * j;
        __nv_bfloat16 h = __float2bfloat16(acc[j]);
        __nv_bfloat16 l = __float2bfloat16(acc[j] - __bfloat162float(h));
        if (z == 0) { g_Mth [t * 256 + a] = h; g_Mtl [t * 256 + a] = l; }
        else        { g_C1th[t * 256 + a] = h; g_C1tl[t * 256 + a] = l; }
    }
}

// Bt (n-major, bf16 hi/lo): g_Bth[j*256+k] = W1[j*512+256+k]
__global__ void k_prepBt(const float* __restrict__ W1) {
    int j = blockIdx.x, k = threadIdx.x;
    float v = W1[j * 512 + 256 + k];
    __nv_bfloat16 h = __float2bfloat16(v);
    g_Bth[j * 256 + k] = h;
    g_Btl[j * 256 + k] = __float2bfloat16(v - __bfloat162float(h));
}

// ---------------- ue fp32 -> bf16 hi/lo split -------------------------------------
__global__ void k_cvt(const float4* __restrict__ src) {
    size_t i = (size_t)blockIdx.x * 256 + threadIdx.x;
    float4 v = src[i];
    __nv_bfloat16 h0 = __float2bfloat16(v.x), h1 = __float2bfloat16(v.y);
    __nv_bfloat16 h2 = __float2bfloat16(v.z), h3 = __float2bfloat16(v.w);
    __nv_bfloat162* H2 = (__nv_bfloat162*)g_Ah;
    H2[i * 2 + 0] = __halves2bfloat162(h0, h1);
    H2[i * 2 + 1] = __halves2bfloat162(h2, h3);
    __nv_bfloat16 l0 = __float2bfloat16(v.x - __bfloat162float(h0));
    __nv_bfloat16 l1 = __float2bfloat16(v.y - __bfloat162float(h1));
    __nv_bfloat16 l2 = __float2bfloat16(v.z - __bfloat162float(h2));
    __nv_bfloat16 l3 = __float2bfloat16(v.w - __bfloat162float(h3));
    __nv_bfloat162* L2 = (__nv_bfloat162*)g_Al;
    L2[i * 2 + 0] = __halves2bfloat162(l0, l1);
    L2[i * 2 + 1] = __halves2bfloat162(l2, l3);
}

// ---------------- softmax gather: per-uid max/exp/normalized weighted sum --------
// block = 256 threads = 4 uids x 64 lanes; writes g_Wh/g_Wl (bf16 hi/lo, normalized)
__global__ void k_gather(const float* __restrict__ ue) {
    int u    = blockIdx.x * 4 + (threadIdx.x >> 6);
    int lane = threadIdx.x & 63;
    if (u >= UU) return;
    int s = g_off[u], e = g_off[u + 1];

    float mx = -1e30f;
    for (int r = s; r < e; r++) mx = fmaxf(mx, g_sim[g_list[r]]);

    float den = 0.0f;
    float4 acc = make_float4(0.f, 0.f, 0.f, 0.f);
    for (int r = s; r < e; r++) {
        int row = g_list[r];
        float ev = expf(g_sim[row] - mx);
        den += ev;
        float4 v = *(const float4*)&ue[(size_t)row * 256 + lane * 4];
        acc.x += ev * v.x; acc.y += ev * v.y; acc.z += ev * v.z; acc.w += ev * v.w;
    }
    float inv = (e > s) ? (1.0f / den) : 0.0f;
    acc.x *= inv; acc.y *= inv; acc.z *= inv; acc.w *= inv;

    __nv_bfloat16 h0 = __float2bfloat16(acc.x), h1 = __float2bfloat16(acc.y);
    __nv_bfloat16 h2 = __float2bfloat16(acc.z), h3 = __float2bfloat16(acc.w);
    __nv_bfloat162* H2 = (__nv_bfloat162*)&g_Wh[(size_t)u * 256 + lane * 4];
    H2[0] = __halves2bfloat162(h0, h1);
    H2[1] = __halves2bfloat162(h2, h3);
    __nv_bfloat16 l0 = __float2bfloat16(acc.x - __bfloat162float(h0));
    __nv_bfloat16 l1 = __float2bfloat16(acc.y - __bfloat162float(h1));
    __nv_bfloat16 l2 = __float2bfloat16(acc.z - __bfloat162float(h2));
    __nv_bfloat16 l3 = __float2bfloat16(acc.w - __bfloat162float(h3));
    __nv_bfloat162* L2 = (__nv_bfloat162*)&g_Wl[(size_t)u * 256 + lane * 4];
    L2[0] = __halves2bfloat162(l0, l1);
    L2[1] = __halves2bfloat162(l2, l3);
}

// ---------------- tensor-core GEMM (split-bf16, BM=128 BN=128, 2 CTA/SM) --------
// grid = (2, rowBlocks): blockIdx.x = 128-col half (co-resident halves share A in L2)
// MODE 0: g_sim[row] += partial rowsum((A @ M) .* sess)               (A = ue)
// MODE 1: g_D = wsn @ Bt + b1                                          (A = wsn, extra = b1)
// MODE 2: out = relu(A @ C1 + g_D[ids])                                (A = ue)
template<int MODE>
__global__ __launch_bounds__(256, 2)
void k_mma(const float* __restrict__ extra, const int* __restrict__ ids,
           float* __restrict__ outp, int nrows) {
    extern __shared__ __align__(16) char smem[];
    uint32_t sbase = (uint32_t)__cvta_generic_to_shared(smem);
    const int tid  = threadIdx.x;
    const int lane = tid & 31;
    const int wid  = tid >> 5;
    const int mw = wid >> 1, nw = wid & 1;     // 4 x 2 warp grid
    const int blockRow = blockIdx.y * BM;
    const int colBase  = blockIdx.x * BN;

    const __nv_bfloat16* Ahp = (MODE == 1) ? g_Wh : g_Ah;
    const __nv_bfloat16* Alp = (MODE == 1) ? g_Wl : g_Al;
    const __nv_bfloat16* Bth = (MODE == 0) ? g_Mth : ((MODE == 1) ? g_Bth : g_C1th);
    const __nv_bfloat16* Btl = (MODE == 0) ? g_Mtl : ((MODE == 1) ? g_Btl : g_C1tl);

    float acc[2][8][4];
    #pragma unroll
    for (int t = 0; t < 2; t++)
        #pragma unroll
        for (int j = 0; j < 8; j++)
            #pragma unroll
            for (int c = 0; c < 4; c++) acc[t][j][c] = 0.0f;

    // ---- async tile loader (stage s, k-tile kt): 8 cpa16 per thread ----
    auto load_stage = [&](int kt, int s) {
        uint32_t db = sbase + (uint32_t)s * STAGE_BYTES;
        #pragma unroll
        for (int l = 0; l < 2; l++) {
            int u = tid + l * 256;
            int r = u >> 2, ch = u & 3;
            // A hi/lo
            int grow = blockRow + r;
            bool v = grow < nrows;
            size_t ga = (size_t)(v ? grow : 0) * HH + kt * BK + ch * 8;
            cpa16(db + AH_OFF + r * 80 + ch * 16, Ahp + ga, v);
            cpa16(db + AL_OFF + r * 80 + ch * 16, Alp + ga, v);
            // B hi/lo (n-rows colBase..colBase+127)
            size_t gb = (size_t)(colBase + r) * HH + kt * BK + ch * 8;
            cpa16(db + BH_OFF + r * 80 + ch * 16, Bth + gb, true);
            cpa16(db + BL_OFF + r * 80 + ch * 16, Btl + gb, true);
        }
        asm volatile("cp.async.commit_group;" ::: "memory");
    };

    load_stage(0, 0);
    load_stage(1, 1);

    const int NKT = HH / BK;   // 8
    for (int kt = 0; kt < NKT; kt++) {
        if (kt < NKT - 1) asm volatile("cp.async.wait_group 1;" ::: "memory");
        else              asm volatile("cp.async.wait_group 0;" ::: "memory");
        __syncthreads();

        uint32_t sb = sbase + (uint32_t)(kt & 1) * STAGE_BYTES;
        #pragma unroll
        for (int k16 = 0; k16 < BK; k16 += 16) {
            uint32_t ah[2][4], al[2][4];
            #pragma unroll
            for (int t = 0; t < 2; t++) {
                uint32_t ao = (uint32_t)(((mw * 32 + t * 16 + (lane & 15)) * KS
                                          + k16 + ((lane >> 4) << 3)) * 2);
                ldsm4(ah[t], sb + AH_OFF + ao);
                ldsm4(al[t], sb + AL_OFF + ao);
            }
            #pragma unroll
            for (int p = 0; p < 4; p++) {
                uint32_t bo = (uint32_t)(((nw * 64 + p * 16 + (lane & 7) + ((lane >> 4) << 3)) * KS
                                          + k16 + (lane & 8)) * 2);
                uint32_t bh[4], bl[4];
                ldsm4(bh, sb + BH_OFF + bo);
                ldsm4(bl, sb + BL_OFF + bo);
                #pragma unroll
                for (int t = 0; t < 2; t++)
                    #pragma unroll
                    for (int q = 0; q < 2; q++)
                        mma16816(acc[t][p * 2 + q], ah[t], &bh[2 * q]);
                #pragma unroll
                for (int t = 0; t < 2; t++)
                    #pragma unroll
                    for (int q = 0; q < 2; q++)
                        mma16816(acc[t][p * 2 + q], ah[t], &bl[2 * q]);
                #pragma unroll
                for (int t = 0; t < 2; t++)
                    #pragma unroll
                    for (int q = 0; q < 2; q++)
                        mma16816(acc[t][p * 2 + q], al[t], &bh[2 * q]);
            }
        }
        __syncthreads();                                    // stage fully consumed
        if (kt + 2 < NKT) load_stage(kt + 2, kt & 1);       // refill same stage
    }

    const int lr = lane >> 2;           // 0..7
    const int lc = (lane & 3) * 2;      // 0,2,4,6

    if (MODE == 0) {
        float part[2][2] = {{0.f, 0.f}, {0.f, 0.f}};
        #pragma unroll
        for (int t = 0; t < 2; t++) {
            int row0 = blockRow + mw * 32 + t * 16 + lr;
            #pragma unroll
            for (int j = 0; j < 8; j++) {
                int col = colBase + nw * 64 + j * 8 + lc;
                if (row0 < nrows) {
                    float2 s = *(const float2*)&extra[(size_t)row0 * 256 + col];
                    part[t][0] += acc[t][j][0] * s.x + acc[t][j][1] * s.y;
                }
                if (row0 + 8 < nrows) {
                    float2 s = *(const float2*)&extra[(size_t)(row0 + 8) * 256 + col];
                    part[t][1] += acc[t][j][2] * s.x + acc[t][j][3] * s.y;
                }
            }
        }
        #pragma unroll
        for (int t = 0; t < 2; t++)
            #pragma unroll
            for (int h = 0; h < 2; h++) {
                part[t][h] += __shfl_xor_sync(0xffffffffu, part[t][h], 1);
                part[t][h] += __shfl_xor_sync(0xffffffffu, part[t][h], 2);
            }
        __syncthreads();                 // stage reads done before smem reuse
        float* red = (float*)smem;       // [128][2]
        if ((lane & 3) == 0) {
            #pragma unroll
            for (int t = 0; t < 2; t++) {
                red[(mw * 32 + t * 16 + lr) * 2 + nw]     = part[t][0];
                red[(mw * 32 + t * 16 + lr + 8) * 2 + nw] = part[t][1];
            }
        }
        __syncthreads();
        if (tid < 128) {
            int row = blockRow + tid;
            if (row < nrows) {
                float s = red[tid * 2] + red[tid * 2 + 1];
                asm volatile("red.global.add.f32 [%0], %1;"
                             :: "l"(g_sim + row), "f"(s) : "memory");
            }
        }
    } else if (MODE == 1) {
        #pragma unroll
        for (int t = 0; t < 2; t++)
            #pragma unroll
            for (int h = 0; h < 2; h++) {
                int row = blockRow + mw * 32 + t * 16 + lr + h * 8;
                if (row >= nrows) continue;
                #pragma unroll
                for (int j = 0; j < 8; j++) {
                    int col = colBase + nw * 64 + j * 8 + lc;
                    float2 b = *(const float2*)&extra[col];
                    float2 o;
                    o.x = acc[t][j][2 * h + 0] + b.x;
                    o.y = acc[t][j][2 * h + 1] + b.y;
                    *(float2*)&g_D[(size_t)row * 256 + col] = o;
                }
            }
    } else {
        #pragma unroll
        for (int t = 0; t < 2; t++)
            #pragma unroll
            for (int h = 0; h < 2; h++) {
                int row = blockRow + mw * 32 + t * 16 + lr + h * 8;
                if (row >= nrows) continue;
                int uid = ids[row];
                const float* Dr = g_D + (size_t)uid * 256;
                #pragma unroll
                for (int j = 0; j < 8; j++) {
                    int col = colBase + nw * 64 + j * 8 + lc;
                    float2 d = *(const float2*)&Dr[col];
                    float2 o;
                    o.x = fmaxf(acc[t][j][2 * h + 0] + d.x, 0.0f);
                    o.y = fmaxf(acc[t][j][2 * h + 1] + d.y, 0.0f);
                    *(float2*)&outp[(size_t)row * 256 + col] = o;
                }
            }
    }
}

// ---------------- launch ----------------------------------------------------------
extern "C" void kernel_launch(void* const* d_in, const int* in_sizes, int n_in,
                              void* d_out, int out_size) {
    const float* sess = (const float*)d_in[0];
    const float* ue   = (const float*)d_in[1];
    const int*   ids  = (const int*)d_in[2];   // JAX x64 disabled: int32
    const float* Wq   = (const float*)d_in[3];
    const float* Wk   = (const float*)d_in[4];
    const float* Wv   = (const float*)d_in[5];
    const float* W1   = (const float*)d_in[6];
    const float* b1   = (const float*)d_in[7];
    float*       out  = (float*)d_out;
    int N = in_sizes[0] / HH;   // 200000

    static bool attr_set = false;
    if (!attr_set) {
        cudaFuncSetAttribute(k_mma<0>, cudaFuncAttributeMaxDynamicSharedMemorySize, NSTAGE * STAGE_BYTES);
        cudaFuncSetAttribute(k_mma<1>, cudaFuncAttributeMaxDynamicSharedMemorySize, NSTAGE * STAGE_BYTES);
        cudaFuncSetAttribute(k_mma<2>, cudaFuncAttributeMaxDynamicSharedMemorySize, NSTAGE * STAGE_BYTES);
        attr_set = true;
    }

    dim3 gBig(2, (N + BM - 1) / BM);
    dim3 gU(2, (UU + BM - 1) / BM);
    k_zero<<<(NN + 255) / 256, 256>>>();
    k_prepT<<<dim3(8, 8, 2), 256>>>(Wq, Wk, Wv, W1);
    k_prepBt<<<256, 256>>>(W1);
    k_cvt<<<N * (HH / 4) / 256, 256>>>((const float4*)ue);
    k_hist<<<(N + 255) / 256, 256>>>(ids, N);
    k_scan<<<1, 256>>>();
    k_fill<<<(N + 255) / 256, 256>>>(ids, N);
    k_mma<0><<<gBig, 256, NSTAGE * STAGE_BYTES>>>(sess, ids, nullptr, N);
    k_gather<<<(UU + 3) / 4, 256>>>(ue);
    k_mma<1><<<gU, 256, NSTAGE * STAGE_BYTES>>>(b1, nullptr, nullptr, UU);
    k_mma<2><<<gBig, 256, NSTAGE * STAGE_BYTES>>>(nullptr, ids, out, N);
}

// round 9
// speedup vs baseline: 2.2419x; 1.1471x over previous
#include <cuda_runtime.h>
#include <cuda_bf16.h>
#include <cstdint>

#define NN 200000
#define UU 20000
#define HH 256

#define BM 64
#define BN 128
#define BK 32
#define AH_OFF 0
#define AL_OFF 4096
#define BH_OFF 8192
#define BL_OFF 16384
#define STAGE_BYTES 24576
#define NSTAGE 2

// ---------------- scratch (device globals) -------------------------------------
__device__ __align__(16) __nv_bfloat16 g_Ah[(size_t)NN * HH];
__device__ __align__(16) __nv_bfloat16 g_Al[(size_t)NN * HH];
__device__ __align__(16) __nv_bfloat16 g_Wh[(size_t)UU * HH];   // normalized ws hi/lo
__device__ __align__(16) __nv_bfloat16 g_Wl[(size_t)UU * HH];
__device__ __align__(16) __nv_bfloat16 g_Mth [HH * HH], g_Mtl [HH * HH];  // M^T  hi/lo (n-major)
__device__ __align__(16) __nv_bfloat16 g_C1th[HH * HH], g_C1tl[HH * HH];  // C1^T hi/lo
__device__ __align__(16) __nv_bfloat16 g_Bth [HH * HH], g_Btl [HH * HH];  // W1[:,H:]  (n-major) hi/lo
__device__ __align__(16) float    g_D  [UU * HH];
__device__ __align__(16) float    g_sim[NN];
__device__ int g_list[NN];          // CSR row lists
__device__ int g_off [UU + 1];
__device__ int g_cnt [UU];
__device__ int g_cnt2[UU];

// ---------------- helpers -------------------------------------------------------
__device__ __forceinline__ void ldsm4(uint32_t* r, uint32_t addr) {
    asm volatile("ldmatrix.sync.aligned.m8n8.x4.shared.b16 {%0,%1,%2,%3}, [%4];"
                 : "=r"(r[0]), "=r"(r[1]), "=r"(r[2]), "=r"(r[3]) : "r"(addr));
}
__device__ __forceinline__ void mma16816(float* c, const uint32_t* a, const uint32_t* b) {
    asm volatile("mma.sync.aligned.m16n8k16.row.col.f32.bf16.bf16.f32 "
                 "{%0,%1,%2,%3}, {%4,%5,%6,%7}, {%8,%9}, {%0,%1,%2,%3};"
                 : "+f"(c[0]), "+f"(c[1]), "+f"(c[2]), "+f"(c[3])
                 : "r"(a[0]), "r"(a[1]), "r"(a[2]), "r"(a[3]), "r"(b[0]), "r"(b[1]));
}
__device__ __forceinline__ void cpa16(uint32_t dst, const void* src, bool v) {
    int sz = v ? 16 : 0;
    asm volatile("cp.async.cg.shared.global [%0], [%1], 16, %2;"
                 :: "r"(dst), "l"(src), "r"(sz));
}
// swizzled byte offset of (row, 16B-chunk ch) in a 64B-stride tile
__device__ __forceinline__ uint32_t swz(int row, int ch) {
    return (uint32_t)(row * 64 + ((ch ^ ((row >> 1) & 3)) * 16));
}

// ---------------- init scratch -------------------------------------------------
__global__ void k_zero() {
    int idx = blockIdx.x * 256 + threadIdx.x;   // 782 blocks
    if (idx < NN) g_sim[idx] = 0.0f;
    if (idx < UU) { g_cnt[idx] = 0; g_cnt2[idx] = 0; }
}

// ---------------- CSR build: hist -> scan -> fill --------------------------------
__global__ void k_hist(const int* __restrict__ ids, int n) {
    int i = blockIdx.x * 256 + threadIdx.x;
    if (i < n) atomicAdd(&g_cnt[ids[i]], 1);
}
__global__ void k_scan() {             // single block, 256 threads
    __shared__ int ps[256];
    const int C = (UU + 255) / 256;    // 79
    int t = threadIdx.x;
    int s = 0;
    for (int j = 0; j < C; j++) { int i = t * C + j; if (i < UU) s += g_cnt[i]; }
    ps[t] = s;
    __syncthreads();
    int acc = 0;
    for (int j = 0; j < t; j++) acc += ps[j];
    int run = acc;
    for (int j = 0; j < C; j++) {
        int i = t * C + j;
        if (i < UU) { g_off[i] = run; run += g_cnt[i]; }
    }
    if (t == 255) g_off[UU] = run;
}
__global__ void k_fill(const int* __restrict__ ids, int n) {
    int i = blockIdx.x * 256 + threadIdx.x;
    if (i < n) {
        int uid = ids[i];
        int pos = g_off[uid] + atomicAdd(&g_cnt2[uid], 1);
        g_list[pos] = i;
    }
}

// ---------------- coalesced precompute GEMMs -----------------------------------
// z==0: M[a,t]  = Wq[a,:]·Wk[t,:]      -> g_Mth/l [t*256+a]
// z==1: C1[a,t] = Wv[a,:]·W1[t,0:256]  -> g_C1th/l[t*256+a]
__global__ void k_prepT(const float* __restrict__ Wq, const float* __restrict__ Wk,
                        const float* __restrict__ Wv, const float* __restrict__ W1) {
    __shared__ float As[32 * 129];
    __shared__ float Bs[32 * 129];
    int z = blockIdx.z;
    int tid = threadIdx.x;
    int abase = blockIdx.y * 32;
    int tbase = blockIdx.x * 32;
    const float* Ag = z ? Wv : Wq;
    int tx = tid & 31, ty = tid >> 5;
    float acc[4] = {0.f, 0.f, 0.f, 0.f};

    for (int kt = 0; kt < 256; kt += 128) {
        #pragma unroll
        for (int i = 0; i < 16; i++) {
            int f = tid + i * 256;
            int r = f >> 7, c = f & 127;
            As[r * 129 + c] = Ag[(abase + r) * 256 + kt + c];
            Bs[r * 129 + c] = z ? W1[(tbase + r) * 512 + kt + c]
                                : Wk[(tbase + r) * 256 + kt + c];
        }
        __syncthreads();
        #pragma unroll 4
        for (int k = 0; k < 128; k++) {
            float av = As[tx * 129 + k];
            #pragma unroll
            for (int j = 0; j < 4; j++) acc[j] += av * Bs[(ty + 8 * j) * 129 + k];
        }
        __syncthreads();
    }
    int a = abase + tx;
    #pragma unroll
    for (int j = 0; j < 4; j++) {
        int t = tbase + ty + 8 * j;
        __nv_bfloat16 h = __float2bfloat16(acc[j]);
        __nv_bfloat16 l = __float2bfloat16(acc[j] - __bfloat162float(h));
        if (z == 0) { g_Mth [t * 256 + a] = h; g_Mtl [t * 256 + a] = l; }
        else        { g_C1th[t * 256 + a] = h; g_C1tl[t * 256 + a] = l; }
    }
}

// Bt (n-major, bf16 hi/lo): g_Bth[j*256+k] = W1[j*512+256+k]
__global__ void k_prepBt(const float* __restrict__ W1) {
    int j = blockIdx.x, k = threadIdx.x;
    float v = W1[j * 512 + 256 + k];
    __nv_bfloat16 h = __float2bfloat16(v);
    g_Bth[j * 256 + k] = h;
    g_Btl[j * 256 + k] = __float2bfloat16(v - __bfloat162float(h));
}

// ---------------- ue fp32 -> bf16 hi/lo split -------------------------------------
__global__ void k_cvt(const float4* __restrict__ src) {
    size_t i = (size_t)blockIdx.x * 256 + threadIdx.x;
    float4 v = src[i];
    __nv_bfloat16 h0 = __float2bfloat16(v.x), h1 = __float2bfloat16(v.y);
    __nv_bfloat16 h2 = __float2bfloat16(v.z), h3 = __float2bfloat16(v.w);
    __nv_bfloat162* H2 = (__nv_bfloat162*)g_Ah;
    H2[i * 2 + 0] = __halves2bfloat162(h0, h1);
    H2[i * 2 + 1] = __halves2bfloat162(h2, h3);
    __nv_bfloat16 l0 = __float2bfloat16(v.x - __bfloat162float(h0));
    __nv_bfloat16 l1 = __float2bfloat16(v.y - __bfloat162float(h1));
    __nv_bfloat16 l2 = __float2bfloat16(v.z - __bfloat162float(h2));
    __nv_bfloat16 l3 = __float2bfloat16(v.w - __bfloat162float(h3));
    __nv_bfloat162* L2 = (__nv_bfloat162*)g_Al;
    L2[i * 2 + 0] = __halves2bfloat162(l0, l1);
    L2[i * 2 + 1] = __halves2bfloat162(l2, l3);
}

// ---------------- softmax gather: per-uid max/exp/normalized weighted sum --------
__global__ void k_gather(const float* __restrict__ ue) {
    int u    = blockIdx.x * 4 + (threadIdx.x >> 6);
    int lane = threadIdx.x & 63;
    if (u >= UU) return;
    int s = g_off[u], e = g_off[u + 1];

    float mx = -1e30f;
    for (int r = s; r < e; r++) mx = fmaxf(mx, g_sim[g_list[r]]);

    float den = 0.0f;
    float4 acc = make_float4(0.f, 0.f, 0.f, 0.f);
    for (int r = s; r < e; r++) {
        int row = g_list[r];
        float ev = expf(g_sim[row] - mx);
        den += ev;
        float4 v = *(const float4*)&ue[(size_t)row * 256 + lane * 4];
        acc.x += ev * v.x; acc.y += ev * v.y; acc.z += ev * v.z; acc.w += ev * v.w;
    }
    float inv = (e > s) ? (1.0f / den) : 0.0f;
    acc.x *= inv; acc.y *= inv; acc.z *= inv; acc.w *= inv;

    __nv_bfloat16 h0 = __float2bfloat16(acc.x), h1 = __float2bfloat16(acc.y);
    __nv_bfloat16 h2 = __float2bfloat16(acc.z), h3 = __float2bfloat16(acc.w);
    __nv_bfloat162* H2 = (__nv_bfloat162*)&g_Wh[(size_t)u * 256 + lane * 4];
    H2[0] = __halves2bfloat162(h0, h1);
    H2[1] = __halves2bfloat162(h2, h3);
    __nv_bfloat16 l0 = __float2bfloat16(acc.x - __bfloat162float(h0));
    __nv_bfloat16 l1 = __float2bfloat16(acc.y - __bfloat162float(h1));
    __nv_bfloat16 l2 = __float2bfloat16(acc.z - __bfloat162float(h2));
    __nv_bfloat16 l3 = __float2bfloat16(acc.w - __bfloat162float(h3));
    __nv_bfloat162* L2 = (__nv_bfloat162*)&g_Wl[(size_t)u * 256 + lane * 4];
    L2[0] = __halves2bfloat162(l0, l1);
    L2[1] = __halves2bfloat162(l2, l3);
}

// ---------------- tensor-core GEMM (split-bf16, BM=64 BN=128, 4 CTA/SM) ----------
// grid = (2, rowBlocks): blockIdx.x = 128-col half
// MODE 0: g_sim[row] += partial rowsum((A @ M) .* sess)               (A = ue)
// MODE 1: g_D = wsn @ Bt + b1                                          (A = wsn, extra = b1)
// MODE 2: out = relu(A @ C1 + g_D[ids])                                (A = ue)
template<int MODE>
__global__ __launch_bounds__(128, 4)
void k_mma(const float* __restrict__ extra, const int* __restrict__ ids,
           float* __restrict__ outp, int nrows) {
    extern __shared__ __align__(16) char smem[];
    uint32_t sbase = (uint32_t)__cvta_generic_to_shared(smem);
    const int tid  = threadIdx.x;
    const int lane = tid & 31;
    const int wid  = tid >> 5;                 // 0..3
    const int mw = wid >> 1, nw = wid & 1;     // 2 x 2 warp grid, warp tile 32x64
    const int blockRow = blockIdx.y * BM;
    const int colBase  = blockIdx.x * BN;

    const __nv_bfloat16* Ahp = (MODE == 1) ? g_Wh : g_Ah;
    const __nv_bfloat16* Alp = (MODE == 1) ? g_Wl : g_Al;
    const __nv_bfloat16* Bth = (MODE == 0) ? g_Mth : ((MODE == 1) ? g_Bth : g_C1th);
    const __nv_bfloat16* Btl = (MODE == 0) ? g_Mtl : ((MODE == 1) ? g_Btl : g_C1tl);

    float acc[2][8][4];
    #pragma unroll
    for (int t = 0; t < 2; t++)
        #pragma unroll
        for (int j = 0; j < 8; j++)
            #pragma unroll
            for (int c = 0; c < 4; c++) acc[t][j][c] = 0.0f;

    // ---- async tile loader (stage s, k-tile kt): 12 cpa16 per thread ----
    auto load_stage = [&](int kt, int s) {
        uint32_t db = sbase + (uint32_t)s * STAGE_BYTES;
        #pragma unroll
        for (int l = 0; l < 2; l++) {           // A hi/lo: 64 rows x 4 chunks
            int u = tid + l * 128;
            int r = u >> 2, ch = u & 3;
            int grow = blockRow + r;
            bool v = grow < nrows;
            size_t ga = (size_t)(v ? grow : 0) * HH + kt * BK + ch * 8;
            uint32_t dst = swz(r, ch);
            cpa16(db + AH_OFF + dst, Ahp + ga, v);
            cpa16(db + AL_OFF + dst, Alp + ga, v);
        }
        #pragma unroll
        for (int l = 0; l < 4; l++) {           // B hi/lo: 128 rows x 4 chunks
            int u = tid + l * 128;
            int r = u >> 2, ch = u & 3;
            size_t gb = (size_t)(colBase + r) * HH + kt * BK + ch * 8;
            uint32_t dst = swz(r, ch);
            cpa16(db + BH_OFF + dst, Bth + gb, true);
            cpa16(db + BL_OFF + dst, Btl + gb, true);
        }
        asm volatile("cp.async.commit_group;" ::: "memory");
    };

    load_stage(0, 0);
    load_stage(1, 1);

    const int NKT = HH / BK;   // 8
    for (int kt = 0; kt < NKT; kt++) {
        if (kt < NKT - 1) asm volatile("cp.async.wait_group 1;" ::: "memory");
        else              asm volatile("cp.async.wait_group 0;" ::: "memory");
        __syncthreads();

        uint32_t sb = sbase + (uint32_t)(kt & 1) * STAGE_BYTES;
        #pragma unroll
        for (int k16 = 0; k16 < BK; k16 += 16) {
            uint32_t ah[2][4], al[2][4];
            #pragma unroll
            for (int t = 0; t < 2; t++) {
                int arow = mw * 32 + t * 16 + (lane & 15);
                int cb = (k16 >> 3) + (lane >> 4);
                uint32_t ao = swz(arow, cb);
                ldsm4(ah[t], sb + AH_OFF + ao);
                ldsm4(al[t], sb + AL_OFF + ao);
            }
            #pragma unroll
            for (int p = 0; p < 4; p++) {
                int brow = nw * 64 + p * 16 + (lane & 7) + ((lane >> 4) << 3);
                int cb = (k16 >> 3) + ((lane >> 3) & 1);
                uint32_t bo = swz(brow, cb);
                uint32_t bh[4], bl[4];
                ldsm4(bh, sb + BH_OFF + bo);
                ldsm4(bl, sb + BL_OFF + bo);
                #pragma unroll
                for (int t = 0; t < 2; t++)
                    #pragma unroll
                    for (int q = 0; q < 2; q++)
                        mma16816(acc[t][p * 2 + q], ah[t], &bh[2 * q]);
                #pragma unroll
                for (int t = 0; t < 2; t++)
                    #pragma unroll
                    for (int q = 0; q < 2; q++)
                        mma16816(acc[t][p * 2 + q], ah[t], &bl[2 * q]);
                #pragma unroll
                for (int t = 0; t < 2; t++)
                    #pragma unroll
                    for (int q = 0; q < 2; q++)
                        mma16816(acc[t][p * 2 + q], al[t], &bh[2 * q]);
            }
        }
        __syncthreads();                                    // stage fully consumed
        if (kt + 2 < NKT) load_stage(kt + 2, kt & 1);       // refill same stage
    }

    const int lr = lane >> 2;           // 0..7
    const int lc = (lane & 3) * 2;      // 0,2,4,6

    if (MODE == 0) {
        float part[2][2] = {{0.f, 0.f}, {0.f, 0.f}};
        #pragma unroll
        for (int t = 0; t < 2; t++) {
            int row0 = blockRow + mw * 32 + t * 16 + lr;
            #pragma unroll
            for (int j = 0; j < 8; j++) {
                int col = colBase + nw * 64 + j * 8 + lc;
                if (row0 < nrows) {
                    float2 s = *(const float2*)&extra[(size_t)row0 * 256 + col];
                    part[t][0] += acc[t][j][0] * s.x + acc[t][j][1] * s.y;
                }
                if (row0 + 8 < nrows) {
                    float2 s = *(const float2*)&extra[(size_t)(row0 + 8) * 256 + col];
                    part[t][1] += acc[t][j][2] * s.x + acc[t][j][3] * s.y;
                }
            }
        }
        #pragma unroll
        for (int t = 0; t < 2; t++)
            #pragma unroll
            for (int h = 0; h < 2; h++) {
                part[t][h] += __shfl_xor_sync(0xffffffffu, part[t][h], 1);
                part[t][h] += __shfl_xor_sync(0xffffffffu, part[t][h], 2);
            }
        __syncthreads();                 // stage reads done before smem reuse
        float* red = (float*)smem;       // [64][2]
        if ((lane & 3) == 0) {
            #pragma unroll
            for (int t = 0; t < 2; t++) {
                red[(mw * 32 + t * 16 + lr) * 2 + nw]     = part[t][0];
                red[(mw * 32 + t * 16 + lr + 8) * 2 + nw] = part[t][1];
            }
        }
        __syncthreads();
        if (tid < 64) {
            int row = blockRow + tid;
            if (row < nrows) {
                float s = red[tid * 2] + red[tid * 2 + 1];
                asm volatile("red.global.add.f32 [%0], %1;"
                             :: "l"(g_sim + row), "f"(s) : "memory");
            }
        }
    } else if (MODE == 1) {
        #pragma unroll
        for (int t = 0; t < 2; t++)
            #pragma unroll
            for (int h = 0; h < 2; h++) {
                int row = blockRow + mw * 32 + t * 16 + lr + h * 8;
                if (row >= nrows) continue;
                #pragma unroll
                for (int j = 0; j < 8; j++) {
                    int col = colBase + nw * 64 + j * 8 + lc;
                    float2 b = *(const float2*)&extra[col];
                    float2 o;
                    o.x = acc[t][j][2 * h + 0] + b.x;
                    o.y = acc[t][j][2 * h + 1] + b.y;
                    *(float2*)&g_D[(size_t)row * 256 + col] = o;
                }
            }
    } else {
        #pragma unroll
        for (int t = 0; t < 2; t++)
            #pragma unroll
            for (int h = 0; h < 2; h++) {
                int row = blockRow + mw * 32 + t * 16 + lr + h * 8;
                if (row >= nrows) continue;
                int uid = ids[row];
                const float* Dr = g_D + (size_t)uid * 256;
                #pragma unroll
                for (int j = 0; j < 8; j++) {
                    int col = colBase + nw * 64 + j * 8 + lc;
                    float2 d = *(const float2*)&Dr[col];
                    float2 o;
                    o.x = fmaxf(acc[t][j][2 * h + 0] + d.x, 0.0f);
                    o.y = fmaxf(acc[t][j][2 * h + 1] + d.y, 0.0f);
                    *(float2*)&outp[(size_t)row * 256 + col] = o;
                }
            }
    }
}

// ---------------- launch ----------------------------------------------------------
extern "C" void kernel_launch(void* const* d_in, const int* in_sizes, int n_in,
                              void* d_out, int out_size) {
    const float* sess = (const float*)d_in[0];
    const float* ue   = (const float*)d_in[1];
    const int*   ids  = (const int*)d_in[2];   // JAX x64 disabled: int32
    const float* Wq   = (const float*)d_in[3];
    const float* Wk   = (const float*)d_in[4];
    const float* Wv   = (const float*)d_in[5];
    const float* W1   = (const float*)d_in[6];
    const float* b1   = (const float*)d_in[7];
    float*       out  = (float*)d_out;
    int N = in_sizes[0] / HH;   // 200000

    static bool attr_set = false;
    if (!attr_set) {
        cudaFuncSetAttribute(k_mma<0>, cudaFuncAttributeMaxDynamicSharedMemorySize, NSTAGE * STAGE_BYTES);
        cudaFuncSetAttribute(k_mma<1>, cudaFuncAttributeMaxDynamicSharedMemorySize, NSTAGE * STAGE_BYTES);
        cudaFuncSetAttribute(k_mma<2>, cudaFuncAttributeMaxDynamicSharedMemorySize, NSTAGE * STAGE_BYTES);
        attr_set = true;
    }

    dim3 gBig(2, (N + BM - 1) / BM);
    dim3 gU(2, (UU + BM - 1) / BM);
    k_zero<<<(NN + 255) / 256, 256>>>();
    k_prepT<<<dim3(8, 8, 2), 256>>>(Wq, Wk, Wv, W1);
    k_prepBt<<<256, 256>>>(W1);
    k_cvt<<<N * (HH / 4) / 256, 256>>>((const float4*)ue);
    k_hist<<<(N + 255) / 256, 256>>>(ids, N);
    k_scan<<<1, 256>>>();
    k_fill<<<(N + 255) / 256, 256>>>(ids, N);
    k_mma<0><<<gBig, 128, NSTAGE * STAGE_BYTES>>>(sess, ids, nullptr, N);
    k_gather<<<(UU + 3) / 4, 256>>>(ue);
    k_mma<1><<<gU, 128, NSTAGE * STAGE_BYTES>>>(b1, nullptr, nullptr, UU);
    k_mma<2><<<gBig, 128, NSTAGE * STAGE_BYTES>>>(nullptr, ids, out, N);
}